// round 1
// baseline (speedup 1.0000x reference)
#include <cuda_runtime.h>
#include <math.h>

// ---------------- problem constants (static shapes) ----------------
#define Bz    4
#define Hh    128
#define Wfull 256
#define Cc    192
#define Ll    (Hh*Wfull)        // 32768
#define HEADS 6
#define HD    32
#define NTOK  64                // tokens per 8x8 window
#define NWIN  512               // windows per image (16*32)
#define BW    (Bz*NWIN)         // 2048 windows total
#define MTOK  (BW*NTOK)         // 131072 window tokens
#define HID   768

// ---------------- scratch (device globals; no allocs allowed) ------
__device__ float g_xw [MTOK*Cc];
__device__ float g_x1w[MTOK*Cc];
__device__ float g_q  [MTOK*Cc];
__device__ float g_kv [MTOK*2*Cc];
__device__ float g_ao [MTOK*Cc];
__device__ float g_xn2[MTOK*Cc];
__device__ float g_h  [MTOK*HID];

// window-token index t -> source/destination row in (B, H*W) layout
// (shift roll by (-4,-4) on the way in; symmetric on the way out)
__device__ __forceinline__ int map_row(int t) {
    int b_  = t >> 6;         // window id
    int n   = t & 63;         // token in window
    int b   = b_ >> 9;        // batch
    int win = b_ & 511;
    int hi  = win >> 5;       // 0..15
    int wi  = win & 31;       // 0..31
    int r   = n >> 3, c = n & 7;
    int hp  = hi * 8 + r;
    int wp  = wi * 8 + c;
    int sh  = (hp + 4) & (Hh - 1);
    int sw  = (wp + 4) & (Wfull - 1);
    return b * Ll + sh * Wfull + sw;
}

// ---------------- LN1 + roll + window partition (x and x1) ----------
__global__ __launch_bounds__(256) void ln1_gather_kernel(
    const float* __restrict__ x, const float* __restrict__ x1,
    const float* __restrict__ g, const float* __restrict__ b)
{
    int warp = (blockIdx.x * blockDim.x + threadIdx.x) >> 5;
    int lane = threadIdx.x & 31;
    if (warp >= MTOK) return;
    int src = map_row(warp);
    const float* xr  = x  + (size_t)src * Cc;
    const float* x1r = x1 + (size_t)src * Cc;

    float v0[6], v1[6];
    float s0 = 0.f, s1 = 0.f, q0 = 0.f, q1 = 0.f;
#pragma unroll
    for (int j = 0; j < 6; j++) {
        v0[j] = xr [lane + 32 * j];
        v1[j] = x1r[lane + 32 * j];
        s0 += v0[j]; q0 += v0[j] * v0[j];
        s1 += v1[j]; q1 += v1[j] * v1[j];
    }
#pragma unroll
    for (int o = 16; o > 0; o >>= 1) {
        s0 += __shfl_xor_sync(0xffffffffu, s0, o);
        q0 += __shfl_xor_sync(0xffffffffu, q0, o);
        s1 += __shfl_xor_sync(0xffffffffu, s1, o);
        q1 += __shfl_xor_sync(0xffffffffu, q1, o);
    }
    float mu0 = s0 * (1.f / Cc), mu1 = s1 * (1.f / Cc);
    float r0 = rsqrtf(q0 * (1.f / Cc) - mu0 * mu0 + 1e-5f);
    float r1 = rsqrtf(q1 * (1.f / Cc) - mu1 * mu1 + 1e-5f);
    size_t ob = (size_t)warp * Cc;
#pragma unroll
    for (int j = 0; j < 6; j++) {
        int e = lane + 32 * j;
        float ge = g[e], be = b[e];
        g_xw [ob + e] = (v0[j] - mu0) * r0 * ge + be;
        g_x1w[ob + e] = (v1[j] - mu1) * r1 * ge + be;
    }
}

// ---------------- LN2 (plain, row-contiguous) -----------------------
__global__ __launch_bounds__(256) void ln2_kernel(
    const float* __restrict__ xin,
    const float* __restrict__ g, const float* __restrict__ b)
{
    int warp = (blockIdx.x * blockDim.x + threadIdx.x) >> 5;
    int lane = threadIdx.x & 31;
    if (warp >= MTOK) return;
    const float* xr = xin + (size_t)warp * Cc;
    float v[6]; float s = 0.f, q = 0.f;
#pragma unroll
    for (int j = 0; j < 6; j++) {
        v[j] = xr[lane + 32 * j];
        s += v[j]; q += v[j] * v[j];
    }
#pragma unroll
    for (int o = 16; o > 0; o >>= 1) {
        s += __shfl_xor_sync(0xffffffffu, s, o);
        q += __shfl_xor_sync(0xffffffffu, q, o);
    }
    float mu = s * (1.f / Cc);
    float rs = rsqrtf(q * (1.f / Cc) - mu * mu + 1e-5f);
    size_t ob = (size_t)warp * Cc;
#pragma unroll
    for (int j = 0; j < 6; j++) {
        int e = lane + 32 * j;
        g_xn2[ob + e] = (v[j] - mu) * rs * g[e] + b[e];
    }
}

// ---------------- attention: one block per (window, head) -----------
__global__ __launch_bounds__(64) void attn_kernel(
    const float* __restrict__ rpb_table, const float* __restrict__ mask)
{
    __shared__ float ks[64][32];
    __shared__ float vs[64][32];

    int head = blockIdx.x % HEADS;
    int b_   = blockIdx.x / HEADS;
    int n    = threadIdx.x;                 // 0..63 (query row)

    // stage K and V for this (window, head)
    const float* kr = g_kv + (size_t)(b_ * 64 + n) * (2 * Cc) + head * HD;
#pragma unroll
    for (int d4 = 0; d4 < 8; d4++) {
        ((float4*)ks[n])[d4] = ((const float4*)kr)[d4];
        ((float4*)vs[n])[d4] = ((const float4*)(kr + Cc))[d4];
    }
    __syncthreads();

    const float scale = 0.17677669529663687f;   // 1/sqrt(32)
    float qv[HD];
    const float* qr = g_q + (size_t)(b_ * 64 + n) * Cc + head * HD;
#pragma unroll
    for (int d = 0; d < HD; d++) qv[d] = qr[d] * scale;

    int rn = n >> 3, cn = n & 7;
    int mbase = (b_ & 511) * (64 * 64) + n * 64;

    float s[64];
    float mx = -1e30f;
#pragma unroll 4
    for (int m = 0; m < 64; m++) {
        float acc = 0.f;
#pragma unroll
        for (int d = 0; d < HD; d++) acc = fmaf(qv[d], ks[m][d], acc);
        int rm = m >> 3, cm = m & 7;
        int idx = (rn - rm + 7) * 15 + (cn - cm + 7);
        acc += rpb_table[idx * HEADS + head] + mask[mbase + m];
        s[m] = acc;
        mx = fmaxf(mx, acc);
    }
    float sum = 0.f;
#pragma unroll
    for (int m = 0; m < 64; m++) { s[m] = __expf(s[m] - mx); sum += s[m]; }
    float inv = 1.f / sum;

    float o[HD];
#pragma unroll
    for (int d = 0; d < HD; d++) o[d] = 0.f;
#pragma unroll 4
    for (int m = 0; m < 64; m++) {
        float p = s[m];
#pragma unroll
        for (int d = 0; d < HD; d++) o[d] = fmaf(p, vs[m][d], o[d]);
    }
    float* outr = g_ao + (size_t)(b_ * 64 + n) * Cc + head * HD;
#pragma unroll
    for (int d = 0; d < HD; d++) outr[d] = o[d] * inv;
}

// ---------------- generic tiled fp32 GEMM: C = A(MxK) * B(KxN) + bias
// EPI: 0 = plain store, 1 = exact GELU, 2 = proj scatter (+shortcut),
//      3 = residual add in place
template <int EPI>
__global__ __launch_bounds__(256) void gemm_kernel(
    const float* __restrict__ A, const float* __restrict__ B,
    const float* __restrict__ bias, float* __restrict__ out,
    const float* __restrict__ src, int M, int N, int K)
{
    __shared__ float As[16][64];
    __shared__ float Bs[16][64];

    int bm = blockIdx.x, bn = blockIdx.y;
    int tid = threadIdx.x;
    int tr = tid >> 4, tc = tid & 15;

    float acc[4][4];
#pragma unroll
    for (int i = 0; i < 4; i++)
#pragma unroll
        for (int j = 0; j < 4; j++) acc[i][j] = 0.f;

    int arow = bm * 64 + (tid >> 2);
    int ak   = (tid & 3) * 4;
    int bk   = tid >> 4;
    int bcol = bn * 64 + (tid & 15) * 4;

    for (int k0 = 0; k0 < K; k0 += 16) {
        float4 a4 = *(const float4*)(A + (size_t)arow * K + k0 + ak);
        float4 b4 = *(const float4*)(B + (size_t)(k0 + bk) * N + bcol);
        As[ak + 0][tid >> 2] = a4.x;
        As[ak + 1][tid >> 2] = a4.y;
        As[ak + 2][tid >> 2] = a4.z;
        As[ak + 3][tid >> 2] = a4.w;
        *(float4*)&Bs[bk][(tid & 15) * 4] = b4;
        __syncthreads();
#pragma unroll
        for (int k = 0; k < 16; k++) {
            float ar[4], br[4];
#pragma unroll
            for (int i = 0; i < 4; i++) ar[i] = As[k][tr * 4 + i];
#pragma unroll
            for (int j = 0; j < 4; j++) br[j] = Bs[k][tc * 4 + j];
#pragma unroll
            for (int i = 0; i < 4; i++)
#pragma unroll
                for (int j = 0; j < 4; j++) acc[i][j] = fmaf(ar[i], br[j], acc[i][j]);
        }
        __syncthreads();
    }

#pragma unroll
    for (int i = 0; i < 4; i++) {
        int m = bm * 64 + tr * 4 + i;
#pragma unroll
        for (int j = 0; j < 4; j++) {
            int n = bn * 64 + tc * 4 + j;
            float v = acc[i][j] + bias[n];
            if (EPI == 0) {
                out[(size_t)m * N + n] = v;
            } else if (EPI == 1) {
                out[(size_t)m * N + n] = 0.5f * v * (1.f + erff(v * 0.7071067811865475f));
            } else if (EPI == 2) {
                int dr = map_row(m);
                out[(size_t)dr * Cc + n] = src[(size_t)dr * Cc + n] + v;
            } else {
                out[(size_t)m * N + n] += v;
            }
        }
    }
}

// ---------------- launch ----------------
extern "C" void kernel_launch(void* const* d_in, const int* in_sizes, int n_in,
                              void* d_out, int out_size)
{
    (void)in_sizes; (void)n_in; (void)out_size;
    const float* x    = (const float*)d_in[0];
    const float* x1   = (const float*)d_in[1];
    const float* mask = (const float*)d_in[2];
    const float* n1g  = (const float*)d_in[3];
    const float* n1b  = (const float*)d_in[4];
    const float* qw   = (const float*)d_in[5];
    const float* qb   = (const float*)d_in[6];
    const float* kvw  = (const float*)d_in[7];
    const float* kvb  = (const float*)d_in[8];
    const float* rpb  = (const float*)d_in[9];
    const float* pw   = (const float*)d_in[10];
    const float* pb   = (const float*)d_in[11];
    const float* n2g  = (const float*)d_in[12];
    const float* n2b  = (const float*)d_in[13];
    const float* f1w  = (const float*)d_in[14];
    const float* f1b  = (const float*)d_in[15];
    const float* f2w  = (const float*)d_in[16];
    const float* f2b  = (const float*)d_in[17];
    float* out = (float*)d_out;

    float *xw, *x1w, *q, *kv, *ao, *xn2, *h;
    cudaGetSymbolAddress((void**)&xw,  g_xw);
    cudaGetSymbolAddress((void**)&x1w, g_x1w);
    cudaGetSymbolAddress((void**)&q,   g_q);
    cudaGetSymbolAddress((void**)&kv,  g_kv);
    cudaGetSymbolAddress((void**)&ao,  g_ao);
    cudaGetSymbolAddress((void**)&xn2, g_xn2);
    cudaGetSymbolAddress((void**)&h,   g_h);

    // 1) LN1 + shift + window partition (both streams)
    ln1_gather_kernel<<<MTOK / 8, 256>>>(x, x1, n1g, n1b);
    // 2) kv = xw @ kv_w + kv_b        (131072 x 384, K=192)
    gemm_kernel<0><<<dim3(MTOK / 64, 6), 256>>>(xw, kvw, kvb, kv, nullptr, MTOK, 2 * Cc, Cc);
    // 3) q = x1w @ q_w + q_b          (131072 x 192, K=192)
    gemm_kernel<0><<<dim3(MTOK / 64, 3), 256>>>(x1w, qw, qb, q, nullptr, MTOK, Cc, Cc);
    // 4) windowed attention with rpb + mask + softmax
    attn_kernel<<<BW * HEADS, 64>>>(rpb, mask);
    // 5) proj + window reverse + unroll-shift + residual -> d_out (= xo)
    gemm_kernel<2><<<dim3(MTOK / 64, 3), 256>>>(ao, pw, pb, out, x, MTOK, Cc, Cc);
    // 6) LN2 on xo
    ln2_kernel<<<MTOK / 8, 256>>>(out, n2g, n2b);
    // 7) fc1 + exact GELU             (131072 x 768, K=192)
    gemm_kernel<1><<<dim3(MTOK / 64, 12), 256>>>(xn2, f1w, f1b, h, nullptr, MTOK, HID, Cc);
    // 8) fc2 + residual into d_out    (131072 x 192, K=768)
    gemm_kernel<3><<<dim3(MTOK / 64, 3), 256>>>(h, f2w, f2b, out, nullptr, MTOK, Cc, HID);
}

// round 2
// speedup vs baseline: 1.7660x; 1.7660x over previous
#include <cuda_runtime.h>
#include <math.h>
#include <stdint.h>

// ---------------- problem constants (static shapes) ----------------
#define Bz    4
#define Hh    128
#define Wfull 256
#define Cc    192
#define Ll    (Hh*Wfull)        // 32768
#define HEADS 6
#define HD    32
#define NTOK  64
#define NWIN  512
#define BW    (Bz*NWIN)         // 2048 windows
#define MTOK  (BW*NTOK)         // 131072 window tokens
#define HID   768

// ---------------- scratch ----------------
__device__ float g_xw [MTOK*Cc];
__device__ float g_x1w[MTOK*Cc];
__device__ float g_q  [MTOK*Cc];
__device__ float g_kv [MTOK*2*Cc];
__device__ float g_ao [MTOK*Cc];
__device__ float g_xn2[MTOK*Cc];
__device__ float g_h  [MTOK*HID];

__device__ __forceinline__ int map_row(int t) {
    int b_  = t >> 6;
    int n   = t & 63;
    int b   = b_ >> 9;
    int win = b_ & 511;
    int hi  = win >> 5;
    int wi  = win & 31;
    int r   = n >> 3, c = n & 7;
    int sh  = (hi * 8 + r + 4) & (Hh - 1);
    int sw  = (wi * 8 + c + 4) & (Wfull - 1);
    return b * Ll + sh * Wfull + sw;
}

__device__ __forceinline__ uint32_t f2tf32(float f) {
    uint32_t r;
    asm("cvt.rna.tf32.f32 %0, %1;" : "=r"(r) : "f"(f));
    return r;
}

// ---------------- LN1 + roll + window partition ----------
__global__ __launch_bounds__(256) void ln1_gather_kernel(
    const float* __restrict__ x, const float* __restrict__ x1,
    const float* __restrict__ g, const float* __restrict__ b)
{
    int warp = (blockIdx.x * blockDim.x + threadIdx.x) >> 5;
    int lane = threadIdx.x & 31;
    if (warp >= MTOK) return;
    int src = map_row(warp);
    const float* xr  = x  + (size_t)src * Cc;
    const float* x1r = x1 + (size_t)src * Cc;

    float v0[6], v1[6];
    float s0 = 0.f, s1 = 0.f, q0 = 0.f, q1 = 0.f;
#pragma unroll
    for (int j = 0; j < 6; j++) {
        v0[j] = xr [lane + 32 * j];
        v1[j] = x1r[lane + 32 * j];
        s0 += v0[j]; q0 += v0[j] * v0[j];
        s1 += v1[j]; q1 += v1[j] * v1[j];
    }
#pragma unroll
    for (int o = 16; o > 0; o >>= 1) {
        s0 += __shfl_xor_sync(0xffffffffu, s0, o);
        q0 += __shfl_xor_sync(0xffffffffu, q0, o);
        s1 += __shfl_xor_sync(0xffffffffu, s1, o);
        q1 += __shfl_xor_sync(0xffffffffu, q1, o);
    }
    float mu0 = s0 * (1.f / Cc), mu1 = s1 * (1.f / Cc);
    float r0 = rsqrtf(q0 * (1.f / Cc) - mu0 * mu0 + 1e-5f);
    float r1 = rsqrtf(q1 * (1.f / Cc) - mu1 * mu1 + 1e-5f);
    size_t ob = (size_t)warp * Cc;
#pragma unroll
    for (int j = 0; j < 6; j++) {
        int e = lane + 32 * j;
        float ge = g[e], be = b[e];
        g_xw [ob + e] = (v0[j] - mu0) * r0 * ge + be;
        g_x1w[ob + e] = (v1[j] - mu1) * r1 * ge + be;
    }
}

// ---------------- LN2 ----------------
__global__ __launch_bounds__(256) void ln2_kernel(
    const float* __restrict__ xin,
    const float* __restrict__ g, const float* __restrict__ b)
{
    int warp = (blockIdx.x * blockDim.x + threadIdx.x) >> 5;
    int lane = threadIdx.x & 31;
    if (warp >= MTOK) return;
    const float* xr = xin + (size_t)warp * Cc;
    float v[6]; float s = 0.f, q = 0.f;
#pragma unroll
    for (int j = 0; j < 6; j++) {
        v[j] = xr[lane + 32 * j];
        s += v[j]; q += v[j] * v[j];
    }
#pragma unroll
    for (int o = 16; o > 0; o >>= 1) {
        s += __shfl_xor_sync(0xffffffffu, s, o);
        q += __shfl_xor_sync(0xffffffffu, q, o);
    }
    float mu = s * (1.f / Cc);
    float rs = rsqrtf(q * (1.f / Cc) - mu * mu + 1e-5f);
    size_t ob = (size_t)warp * Cc;
#pragma unroll
    for (int j = 0; j < 6; j++) {
        int e = lane + 32 * j;
        g_xn2[ob + e] = (v[j] - mu) * rs * g[e] + b[e];
    }
}

// ---------------- attention: one block per (window, head) -----------
// scores live in shared memory (column-per-thread) -> no register spills
__global__ __launch_bounds__(64) void attn_kernel(
    const float* __restrict__ rpb_table, const float* __restrict__ mask)
{
    __shared__ float ks[64][32];
    __shared__ float vs[64][32];
    __shared__ float ss[64][64];   // ss[m][n], thread n owns column n

    int head = blockIdx.x % HEADS;
    int b_   = blockIdx.x / HEADS;
    int n    = threadIdx.x;

    const float* kr = g_kv + (size_t)(b_ * 64 + n) * (2 * Cc) + head * HD;
#pragma unroll
    for (int d4 = 0; d4 < 8; d4++) {
        ((float4*)ks[n])[d4] = ((const float4*)kr)[d4];
        ((float4*)vs[n])[d4] = ((const float4*)(kr + Cc))[d4];
    }
    __syncthreads();

    const float scale = 0.17677669529663687f;
    float qv[HD];
    const float* qr = g_q + (size_t)(b_ * 64 + n) * Cc + head * HD;
#pragma unroll
    for (int d = 0; d < HD; d++) qv[d] = qr[d] * scale;

    int rn = n >> 3, cn = n & 7;
    int mbase = (b_ & 511) * (64 * 64) + n * 64;

    float mx = -1e30f;
#pragma unroll 4
    for (int m = 0; m < 64; m++) {
        float acc = 0.f;
#pragma unroll
        for (int d = 0; d < HD; d++) acc = fmaf(qv[d], ks[m][d], acc);
        int rm = m >> 3, cm = m & 7;
        int idx = (rn - rm + 7) * 15 + (cn - cm + 7);
        acc += rpb_table[idx * HEADS + head] + mask[mbase + m];
        ss[m][n] = acc;
        mx = fmaxf(mx, acc);
    }

    float o[HD];
#pragma unroll
    for (int d = 0; d < HD; d++) o[d] = 0.f;
    float sum = 0.f;
#pragma unroll 4
    for (int m = 0; m < 64; m++) {
        float p = __expf(ss[m][n] - mx);
        sum += p;
#pragma unroll
        for (int d = 0; d < HD; d++) o[d] = fmaf(p, vs[m][d], o[d]);
    }
    float inv = 1.f / sum;
    float* outr = g_ao + (size_t)(b_ * 64 + n) * Cc + head * HD;
#pragma unroll
    for (int d = 0; d < HD; d++) outr[d] = o[d] * inv;
}

// ---------------- tf32 tensor-core GEMM ----------------
// C(MxN) = A(MxK) @ B(KxN) + bias, tile 128x64x32, 256 thr (8 warps: 4m x 2n)
// EPI: 0 plain, 1 GELU, 2 proj scatter (+shortcut), 3 residual add
#define ASTR 36
#define BSTR 68

template <int EPI>
__global__ __launch_bounds__(256) void gemm_tf32_kernel(
    const float* __restrict__ A, const float* __restrict__ B,
    const float* __restrict__ bias, float* __restrict__ out,
    const float* __restrict__ src, int M, int N, int K)
{
    __shared__ uint32_t As[128][ASTR];
    __shared__ uint32_t Bs[32][BSTR];

    int tid  = threadIdx.x;
    int lane = tid & 31;
    int warp = tid >> 5;
    int warpm = warp >> 1;          // 0..3  -> 32 rows each
    int warpn = warp & 1;           // 0..1  -> 32 cols each
    int g   = lane >> 2;            // 0..7
    int tig = lane & 3;             // 0..3

    int bm = blockIdx.x, bn = blockIdx.y;

    float acc[2][4][4];
#pragma unroll
    for (int mi = 0; mi < 2; mi++)
#pragma unroll
        for (int ni = 0; ni < 4; ni++)
#pragma unroll
            for (int r = 0; r < 4; r++) acc[mi][ni][r] = 0.f;

    for (int k0 = 0; k0 < K; k0 += 32) {
        // load A tile: 128 rows x 32 k, 1024 float4
#pragma unroll
        for (int i = 0; i < 4; i++) {
            int idx = tid + i * 256;
            int row = idx >> 3;
            int kc  = (idx & 7) * 4;
            float4 f = *(const float4*)(A + (size_t)(bm * 128 + row) * K + k0 + kc);
            As[row][kc + 0] = f2tf32(f.x);
            As[row][kc + 1] = f2tf32(f.y);
            As[row][kc + 2] = f2tf32(f.z);
            As[row][kc + 3] = f2tf32(f.w);
        }
        // load B tile: 32 k x 64 n, 512 float4
#pragma unroll
        for (int i = 0; i < 2; i++) {
            int idx = tid + i * 256;
            int kr  = idx >> 4;
            int nc  = (idx & 15) * 4;
            float4 f = *(const float4*)(B + (size_t)(k0 + kr) * N + bn * 64 + nc);
            Bs[kr][nc + 0] = f2tf32(f.x);
            Bs[kr][nc + 1] = f2tf32(f.y);
            Bs[kr][nc + 2] = f2tf32(f.z);
            Bs[kr][nc + 3] = f2tf32(f.w);
        }
        __syncthreads();

#pragma unroll
        for (int ks = 0; ks < 32; ks += 8) {
            uint32_t a[2][4], b[4][2];
#pragma unroll
            for (int mi = 0; mi < 2; mi++) {
                int mb = warpm * 32 + mi * 16;
                a[mi][0] = As[mb + g    ][ks + tig];
                a[mi][1] = As[mb + g + 8][ks + tig];
                a[mi][2] = As[mb + g    ][ks + tig + 4];
                a[mi][3] = As[mb + g + 8][ks + tig + 4];
            }
#pragma unroll
            for (int ni = 0; ni < 4; ni++) {
                int nb = warpn * 32 + ni * 8 + g;
                b[ni][0] = Bs[ks + tig    ][nb];
                b[ni][1] = Bs[ks + tig + 4][nb];
            }
#pragma unroll
            for (int mi = 0; mi < 2; mi++)
#pragma unroll
                for (int ni = 0; ni < 4; ni++) {
                    asm volatile(
                        "mma.sync.aligned.m16n8k8.row.col.f32.tf32.tf32.f32 "
                        "{%0,%1,%2,%3},{%4,%5,%6,%7},{%8,%9},{%0,%1,%2,%3};"
                        : "+f"(acc[mi][ni][0]), "+f"(acc[mi][ni][1]),
                          "+f"(acc[mi][ni][2]), "+f"(acc[mi][ni][3])
                        : "r"(a[mi][0]), "r"(a[mi][1]), "r"(a[mi][2]), "r"(a[mi][3]),
                          "r"(b[ni][0]), "r"(b[ni][1]));
                }
        }
        __syncthreads();
    }

    // epilogue: c0,c1 -> (r0, c), (r0, c+1); c2,c3 -> (r0+8, ...)
#pragma unroll
    for (int mi = 0; mi < 2; mi++) {
#pragma unroll
        for (int ni = 0; ni < 4; ni++) {
            int r0 = bm * 128 + warpm * 32 + mi * 16 + g;
            int c  = bn * 64  + warpn * 32 + ni * 8 + tig * 2;
            float bia0 = bias[c], bia1 = bias[c + 1];
#pragma unroll
            for (int half = 0; half < 2; half++) {
                int r = r0 + half * 8;
                float v0 = acc[mi][ni][half * 2 + 0] + bia0;
                float v1 = acc[mi][ni][half * 2 + 1] + bia1;
                if (EPI == 0) {
                    *(float2*)(out + (size_t)r * N + c) = make_float2(v0, v1);
                } else if (EPI == 1) {
                    v0 = 0.5f * v0 * (1.f + erff(v0 * 0.7071067811865475f));
                    v1 = 0.5f * v1 * (1.f + erff(v1 * 0.7071067811865475f));
                    *(float2*)(out + (size_t)r * N + c) = make_float2(v0, v1);
                } else if (EPI == 2) {
                    int dr = map_row(r);
                    size_t o0 = (size_t)dr * Cc + c;
                    out[o0]     = src[o0]     + v0;
                    out[o0 + 1] = src[o0 + 1] + v1;
                } else {
                    size_t o0 = (size_t)r * N + c;
                    out[o0]     += v0;
                    out[o0 + 1] += v1;
                }
            }
        }
    }
}

// ---------------- launch ----------------
extern "C" void kernel_launch(void* const* d_in, const int* in_sizes, int n_in,
                              void* d_out, int out_size)
{
    (void)in_sizes; (void)n_in; (void)out_size;
    const float* x    = (const float*)d_in[0];
    const float* x1   = (const float*)d_in[1];
    const float* mask = (const float*)d_in[2];
    const float* n1g  = (const float*)d_in[3];
    const float* n1b  = (const float*)d_in[4];
    const float* qw   = (const float*)d_in[5];
    const float* qb   = (const float*)d_in[6];
    const float* kvw  = (const float*)d_in[7];
    const float* kvb  = (const float*)d_in[8];
    const float* rpb  = (const float*)d_in[9];
    const float* pw   = (const float*)d_in[10];
    const float* pb   = (const float*)d_in[11];
    const float* n2g  = (const float*)d_in[12];
    const float* n2b  = (const float*)d_in[13];
    const float* f1w  = (const float*)d_in[14];
    const float* f1b  = (const float*)d_in[15];
    const float* f2w  = (const float*)d_in[16];
    const float* f2b  = (const float*)d_in[17];
    float* out = (float*)d_out;

    float *xw, *x1w, *q, *kv, *ao, *xn2, *h;
    cudaGetSymbolAddress((void**)&xw,  g_xw);
    cudaGetSymbolAddress((void**)&x1w, g_x1w);
    cudaGetSymbolAddress((void**)&q,   g_q);
    cudaGetSymbolAddress((void**)&kv,  g_kv);
    cudaGetSymbolAddress((void**)&ao,  g_ao);
    cudaGetSymbolAddress((void**)&xn2, g_xn2);
    cudaGetSymbolAddress((void**)&h,   g_h);

    ln1_gather_kernel<<<MTOK / 8, 256>>>(x, x1, n1g, n1b);
    gemm_tf32_kernel<0><<<dim3(MTOK / 128, 6), 256>>>(xw, kvw, kvb, kv, nullptr, MTOK, 2 * Cc, Cc);
    gemm_tf32_kernel<0><<<dim3(MTOK / 128, 3), 256>>>(x1w, qw, qb, q, nullptr, MTOK, Cc, Cc);
    attn_kernel<<<BW * HEADS, 64>>>(rpb, mask);
    gemm_tf32_kernel<2><<<dim3(MTOK / 128, 3), 256>>>(ao, pw, pb, out, x, MTOK, Cc, Cc);
    ln2_kernel<<<MTOK / 8, 256>>>(out, n2g, n2b);
    gemm_tf32_kernel<1><<<dim3(MTOK / 128, 12), 256>>>(xn2, f1w, f1b, h, nullptr, MTOK, HID, Cc);
    gemm_tf32_kernel<3><<<dim3(MTOK / 128, 3), 256>>>(h, f2w, f2b, out, nullptr, MTOK, Cc, HID);
}

// round 3
// speedup vs baseline: 1.9558x; 1.1075x over previous
#include <cuda_runtime.h>
#include <math.h>
#include <stdint.h>

// ---------------- problem constants ----------------
#define Bz    4
#define Hh    128
#define Wfull 256
#define Cc    192
#define Ll    (Hh*Wfull)
#define HEADS 6
#define HD    32
#define NTOK  64
#define NWIN  512
#define BW    (Bz*NWIN)         // 2048 windows
#define MTOK  (BW*NTOK)         // 131072 window tokens
#define HID   768

// ---------------- scratch ----------------
__device__ float g_xw [MTOK*Cc];
__device__ float g_x1w[MTOK*Cc];
__device__ float g_q  [MTOK*Cc];
__device__ float g_kv [MTOK*2*Cc];
__device__ float g_ao [MTOK*Cc];
__device__ float g_xn2[MTOK*Cc];
__device__ float g_h  [MTOK*HID];

__device__ __forceinline__ int map_row(int t) {
    int b_  = t >> 6;
    int n   = t & 63;
    int b   = b_ >> 9;
    int win = b_ & 511;
    int hi  = win >> 5;
    int wi  = win & 31;
    int r   = n >> 3, c = n & 7;
    int sh  = (hi * 8 + r + 4) & (Hh - 1);
    int sw  = (wi * 8 + c + 4) & (Wfull - 1);
    return b * Ll + sh * Wfull + sw;
}

__device__ __forceinline__ uint32_t f2tf32(float f) {
    uint32_t r;
    asm("cvt.rna.tf32.f32 %0, %1;" : "=r"(r) : "f"(f));
    return r;
}

__device__ __forceinline__ uint32_t smem_u32(const void* p) {
    return (uint32_t)__cvta_generic_to_shared(p);
}

// ---------------- LN1 + roll + window partition ----------
__global__ __launch_bounds__(256) void ln1_gather_kernel(
    const float* __restrict__ x, const float* __restrict__ x1,
    const float* __restrict__ g, const float* __restrict__ b)
{
    int warp = (blockIdx.x * blockDim.x + threadIdx.x) >> 5;
    int lane = threadIdx.x & 31;
    if (warp >= MTOK) return;
    int src = map_row(warp);
    const float* xr  = x  + (size_t)src * Cc;
    const float* x1r = x1 + (size_t)src * Cc;

    float v0[6], v1[6];
    float s0 = 0.f, s1 = 0.f, q0 = 0.f, q1 = 0.f;
#pragma unroll
    for (int j = 0; j < 6; j++) {
        v0[j] = xr [lane + 32 * j];
        v1[j] = x1r[lane + 32 * j];
        s0 += v0[j]; q0 += v0[j] * v0[j];
        s1 += v1[j]; q1 += v1[j] * v1[j];
    }
#pragma unroll
    for (int o = 16; o > 0; o >>= 1) {
        s0 += __shfl_xor_sync(0xffffffffu, s0, o);
        q0 += __shfl_xor_sync(0xffffffffu, q0, o);
        s1 += __shfl_xor_sync(0xffffffffu, s1, o);
        q1 += __shfl_xor_sync(0xffffffffu, q1, o);
    }
    float mu0 = s0 * (1.f / Cc), mu1 = s1 * (1.f / Cc);
    float r0 = rsqrtf(q0 * (1.f / Cc) - mu0 * mu0 + 1e-5f);
    float r1 = rsqrtf(q1 * (1.f / Cc) - mu1 * mu1 + 1e-5f);
    size_t ob = (size_t)warp * Cc;
#pragma unroll
    for (int j = 0; j < 6; j++) {
        int e = lane + 32 * j;
        float ge = g[e], be = b[e];
        g_xw [ob + e] = (v0[j] - mu0) * r0 * ge + be;
        g_x1w[ob + e] = (v1[j] - mu1) * r1 * ge + be;
    }
}

// ---------------- LN2 ----------------
__global__ __launch_bounds__(256) void ln2_kernel(
    const float* __restrict__ xin,
    const float* __restrict__ g, const float* __restrict__ b)
{
    int warp = (blockIdx.x * blockDim.x + threadIdx.x) >> 5;
    int lane = threadIdx.x & 31;
    if (warp >= MTOK) return;
    const float* xr = xin + (size_t)warp * Cc;
    float v[6]; float s = 0.f, q = 0.f;
#pragma unroll
    for (int j = 0; j < 6; j++) {
        v[j] = xr[lane + 32 * j];
        s += v[j]; q += v[j] * v[j];
    }
#pragma unroll
    for (int o = 16; o > 0; o >>= 1) {
        s += __shfl_xor_sync(0xffffffffu, s, o);
        q += __shfl_xor_sync(0xffffffffu, q, o);
    }
    float mu = s * (1.f / Cc);
    float rs = rsqrtf(q * (1.f / Cc) - mu * mu + 1e-5f);
    size_t ob = (size_t)warp * Cc;
#pragma unroll
    for (int j = 0; j < 6; j++) {
        int e = lane + 32 * j;
        g_xn2[ob + e] = (v[j] - mu) * rs * g[e] + b[e];
    }
}

// ---------------- attention v3 ---------------------------------------
// grid: 6 heads x 512 window-groups; block 256 = 4 windows x 64 queries
// single pass (no max subtraction), float4 broadcast loads, rpb in smem
__global__ __launch_bounds__(256) void attn_kernel(
    const float* __restrict__ rpb_table, const float* __restrict__ mask)
{
    __shared__ float rpb_s[64 * 64];    // [m][n] for this head

    int h   = blockIdx.x >> 9;          // 0..5
    int wg  = blockIdx.x & 511;
    int sub = threadIdx.x >> 6;
    int n   = threadIdx.x & 63;
    int b_  = wg * 4 + sub;

    for (int i = threadIdx.x; i < 4096; i += 256) {
        int mm = i >> 6, nn = i & 63;
        int idx = ((nn >> 3) - (mm >> 3) + 7) * 15 + ((nn & 7) - (mm & 7) + 7);
        rpb_s[i] = __ldg(rpb_table + idx * HEADS + h);
    }
    __syncthreads();

    const float scale = 0.17677669529663687f;
    const float* qr = g_q + (size_t)(b_ * 64 + n) * Cc + h * HD;
    float qv[HD];
#pragma unroll
    for (int j = 0; j < 8; j++) {
        float4 f = __ldg((const float4*)qr + j);
        qv[4*j+0] = f.x * scale; qv[4*j+1] = f.y * scale;
        qv[4*j+2] = f.z * scale; qv[4*j+3] = f.w * scale;
    }

    float o[HD];
#pragma unroll
    for (int d = 0; d < HD; d++) o[d] = 0.f;
    float sum = 0.f;

    const float* mrow = mask + (size_t)(b_ & 511) * 4096 + n * 64;
    const float4* kvb = (const float4*)(g_kv + (size_t)(b_ * 64) * (2 * Cc) + h * HD);
    // row m: kvb + m*96 (K), + 48 more (V)

    for (int m0 = 0; m0 < 64; m0 += 4) {
        float4 mk = __ldg((const float4*)(mrow + m0));
        float mks[4] = {mk.x, mk.y, mk.z, mk.w};
#pragma unroll
        for (int mm = 0; mm < 4; mm++) {
            int m = m0 + mm;
            const float4* kr = kvb + m * 96;
            float a0 = 0.f, a1 = 0.f;
#pragma unroll
            for (int j = 0; j < 8; j++) {
                float4 k4 = __ldg(kr + j);
                a0 = fmaf(qv[4*j+0], k4.x, a0);
                a1 = fmaf(qv[4*j+1], k4.y, a1);
                a0 = fmaf(qv[4*j+2], k4.z, a0);
                a1 = fmaf(qv[4*j+3], k4.w, a1);
            }
            float p = __expf(a0 + a1 + rpb_s[m * 64 + n] + mks[mm]);
            sum += p;
            const float4* vr = kr + 48;
#pragma unroll
            for (int j = 0; j < 8; j++) {
                float4 v4 = __ldg(vr + j);
                o[4*j+0] = fmaf(p, v4.x, o[4*j+0]);
                o[4*j+1] = fmaf(p, v4.y, o[4*j+1]);
                o[4*j+2] = fmaf(p, v4.z, o[4*j+2]);
                o[4*j+3] = fmaf(p, v4.w, o[4*j+3]);
            }
        }
    }

    float inv = 1.f / sum;
    float4* outr = (float4*)(g_ao + (size_t)(b_ * 64 + n) * Cc + h * HD);
#pragma unroll
    for (int j = 0; j < 8; j++)
        outr[j] = make_float4(o[4*j+0]*inv, o[4*j+1]*inv, o[4*j+2]*inv, o[4*j+3]*inv);
}

// ---------------- tf32 GEMM, cp.async double-buffered ----------------
// tile 128x64x32, 256 thr (8 warps: 4m x 2n)
#define ASTR 36
#define BSTR 68

template <int EPI>
__global__ __launch_bounds__(256) void gemm_tf32_kernel(
    const float* __restrict__ A, const float* __restrict__ B,
    const float* __restrict__ bias, float* __restrict__ out,
    const float* __restrict__ src, int M, int N, int K)
{
    __shared__ float As[2][128][ASTR];
    __shared__ float Bs[2][32][BSTR];

    int tid  = threadIdx.x;
    int lane = tid & 31;
    int warp = tid >> 5;
    int warpm = warp >> 1;
    int warpn = warp & 1;
    int g   = lane >> 2;
    int tig = lane & 3;

    int bm = blockIdx.x, bn = blockIdx.y;

    float acc[2][4][4];
#pragma unroll
    for (int mi = 0; mi < 2; mi++)
#pragma unroll
        for (int ni = 0; ni < 4; ni++)
#pragma unroll
            for (int r = 0; r < 4; r++) acc[mi][ni][r] = 0.f;

    // async copy of one K-step tile into buffer `buf`
    auto copy_tile = [&](int buf, int k0) {
#pragma unroll
        for (int i = 0; i < 4; i++) {
            int c   = tid + i * 256;
            int row = c >> 3;
            int kc  = (c & 7) * 4;
            const float* gp = A + (size_t)(bm * 128 + row) * K + k0 + kc;
            uint32_t dp = smem_u32(&As[buf][row][kc]);
            asm volatile("cp.async.ca.shared.global [%0], [%1], 16;" :: "r"(dp), "l"(gp));
        }
#pragma unroll
        for (int i = 0; i < 2; i++) {
            int c  = tid + i * 256;
            int kr = c >> 4;
            int nc = (c & 15) * 4;
            const float* gp = B + (size_t)(k0 + kr) * N + bn * 64 + nc;
            uint32_t dp = smem_u32(&Bs[buf][kr][nc]);
            asm volatile("cp.async.ca.shared.global [%0], [%1], 16;" :: "r"(dp), "l"(gp));
        }
        asm volatile("cp.async.commit_group;");
    };

    copy_tile(0, 0);

    int buf = 0;
    for (int k0 = 0; k0 < K; k0 += 32, buf ^= 1) {
        if (k0 + 32 < K) {
            copy_tile(buf ^ 1, k0 + 32);
            asm volatile("cp.async.wait_group 1;");
        } else {
            asm volatile("cp.async.wait_group 0;");
        }
        __syncthreads();

#pragma unroll
        for (int ks = 0; ks < 32; ks += 8) {
            uint32_t a[2][4], b[4][2];
#pragma unroll
            for (int mi = 0; mi < 2; mi++) {
                int mb = warpm * 32 + mi * 16;
                a[mi][0] = f2tf32(As[buf][mb + g    ][ks + tig]);
                a[mi][1] = f2tf32(As[buf][mb + g + 8][ks + tig]);
                a[mi][2] = f2tf32(As[buf][mb + g    ][ks + tig + 4]);
                a[mi][3] = f2tf32(As[buf][mb + g + 8][ks + tig + 4]);
            }
#pragma unroll
            for (int ni = 0; ni < 4; ni++) {
                int nb = warpn * 32 + ni * 8 + g;
                b[ni][0] = f2tf32(Bs[buf][ks + tig    ][nb]);
                b[ni][1] = f2tf32(Bs[buf][ks + tig + 4][nb]);
            }
#pragma unroll
            for (int mi = 0; mi < 2; mi++)
#pragma unroll
                for (int ni = 0; ni < 4; ni++) {
                    asm volatile(
                        "mma.sync.aligned.m16n8k8.row.col.f32.tf32.tf32.f32 "
                        "{%0,%1,%2,%3},{%4,%5,%6,%7},{%8,%9},{%0,%1,%2,%3};"
                        : "+f"(acc[mi][ni][0]), "+f"(acc[mi][ni][1]),
                          "+f"(acc[mi][ni][2]), "+f"(acc[mi][ni][3])
                        : "r"(a[mi][0]), "r"(a[mi][1]), "r"(a[mi][2]), "r"(a[mi][3]),
                          "r"(b[ni][0]), "r"(b[ni][1]));
                }
        }
        __syncthreads();
    }

#pragma unroll
    for (int mi = 0; mi < 2; mi++) {
#pragma unroll
        for (int ni = 0; ni < 4; ni++) {
            int r0 = bm * 128 + warpm * 32 + mi * 16 + g;
            int c  = bn * 64  + warpn * 32 + ni * 8 + tig * 2;
            float bia0 = bias[c], bia1 = bias[c + 1];
#pragma unroll
            for (int half = 0; half < 2; half++) {
                int r = r0 + half * 8;
                float v0 = acc[mi][ni][half * 2 + 0] + bia0;
                float v1 = acc[mi][ni][half * 2 + 1] + bia1;
                if (EPI == 0) {
                    *(float2*)(out + (size_t)r * N + c) = make_float2(v0, v1);
                } else if (EPI == 1) {
                    v0 = 0.5f * v0 * (1.f + erff(v0 * 0.7071067811865475f));
                    v1 = 0.5f * v1 * (1.f + erff(v1 * 0.7071067811865475f));
                    *(float2*)(out + (size_t)r * N + c) = make_float2(v0, v1);
                } else if (EPI == 2) {
                    int dr = map_row(r);
                    size_t o0 = (size_t)dr * Cc + c;
                    out[o0]     = src[o0]     + v0;
                    out[o0 + 1] = src[o0 + 1] + v1;
                } else {
                    size_t o0 = (size_t)r * N + c;
                    out[o0]     += v0;
                    out[o0 + 1] += v1;
                }
            }
        }
    }
}

// ---------------- launch ----------------
extern "C" void kernel_launch(void* const* d_in, const int* in_sizes, int n_in,
                              void* d_out, int out_size)
{
    (void)in_sizes; (void)n_in; (void)out_size;
    const float* x    = (const float*)d_in[0];
    const float* x1   = (const float*)d_in[1];
    const float* mask = (const float*)d_in[2];
    const float* n1g  = (const float*)d_in[3];
    const float* n1b  = (const float*)d_in[4];
    const float* qw   = (const float*)d_in[5];
    const float* qb   = (const float*)d_in[6];
    const float* kvw  = (const float*)d_in[7];
    const float* kvb  = (const float*)d_in[8];
    const float* rpb  = (const float*)d_in[9];
    const float* pw   = (const float*)d_in[10];
    const float* pb   = (const float*)d_in[11];
    const float* n2g  = (const float*)d_in[12];
    const float* n2b  = (const float*)d_in[13];
    const float* f1w  = (const float*)d_in[14];
    const float* f1b  = (const float*)d_in[15];
    const float* f2w  = (const float*)d_in[16];
    const float* f2b  = (const float*)d_in[17];
    float* out = (float*)d_out;

    float *xw, *x1w, *q, *kv, *ao, *xn2, *h;
    cudaGetSymbolAddress((void**)&xw,  g_xw);
    cudaGetSymbolAddress((void**)&x1w, g_x1w);
    cudaGetSymbolAddress((void**)&q,   g_q);
    cudaGetSymbolAddress((void**)&kv,  g_kv);
    cudaGetSymbolAddress((void**)&ao,  g_ao);
    cudaGetSymbolAddress((void**)&xn2, g_xn2);
    cudaGetSymbolAddress((void**)&h,   g_h);

    ln1_gather_kernel<<<MTOK / 8, 256>>>(x, x1, n1g, n1b);
    gemm_tf32_kernel<0><<<dim3(MTOK / 128, 6), 256>>>(xw, kvw, kvb, kv, nullptr, MTOK, 2 * Cc, Cc);
    gemm_tf32_kernel<0><<<dim3(MTOK / 128, 3), 256>>>(x1w, qw, qb, q, nullptr, MTOK, Cc, Cc);
    attn_kernel<<<HEADS * 512, 256>>>(rpb, mask);
    gemm_tf32_kernel<2><<<dim3(MTOK / 128, 3), 256>>>(ao, pw, pb, out, x, MTOK, Cc, Cc);
    ln2_kernel<<<MTOK / 8, 256>>>(out, n2g, n2b);
    gemm_tf32_kernel<1><<<dim3(MTOK / 128, 12), 256>>>(xn2, f1w, f1b, h, nullptr, MTOK, HID, Cc);
    gemm_tf32_kernel<3><<<dim3(MTOK / 128, 3), 256>>>(h, f2w, f2b, out, nullptr, MTOK, Cc, HID);
}

// round 4
// speedup vs baseline: 2.8001x; 1.4317x over previous
#include <cuda_runtime.h>
#include <math.h>
#include <stdint.h>

// ---------------- problem constants ----------------
#define Bz    4
#define Hh    128
#define Wfull 256
#define Cc    192
#define Ll    (Hh*Wfull)
#define HEADS 6
#define HD    32
#define NTOK  64
#define NWIN  512
#define BW    (Bz*NWIN)         // 2048 windows
#define MTOK  (BW*NTOK)         // 131072 window tokens
#define HID   768

// ---------------- scratch ----------------
__device__ float g_xw [MTOK*Cc];
__device__ float g_x1w[MTOK*Cc];
__device__ float g_q  [MTOK*Cc];
__device__ float g_kv [MTOK*2*Cc];
__device__ float g_ao [MTOK*Cc];
__device__ float g_xn2[MTOK*Cc];
__device__ float g_h  [MTOK*HID];

__device__ __forceinline__ int map_row(int t) {
    int b_  = t >> 6;
    int n   = t & 63;
    int b   = b_ >> 9;
    int win = b_ & 511;
    int hi  = win >> 5;
    int wi  = win & 31;
    int r   = n >> 3, c = n & 7;
    int sh  = (hi * 8 + r + 4) & (Hh - 1);
    int sw  = (wi * 8 + c + 4) & (Wfull - 1);
    return b * Ll + sh * Wfull + sw;
}

__device__ __forceinline__ uint32_t f2tf32(float f) {
    uint32_t r;
    asm("cvt.rna.tf32.f32 %0, %1;" : "=r"(r) : "f"(f));
    return r;
}

__device__ __forceinline__ uint32_t smem_u32(const void* p) {
    return (uint32_t)__cvta_generic_to_shared(p);
}

// ---------------- LN1 + roll + window partition ----------
__global__ __launch_bounds__(256) void ln1_gather_kernel(
    const float* __restrict__ x, const float* __restrict__ x1,
    const float* __restrict__ g, const float* __restrict__ b)
{
    int warp = (blockIdx.x * blockDim.x + threadIdx.x) >> 5;
    int lane = threadIdx.x & 31;
    if (warp >= MTOK) return;
    int src = map_row(warp);
    const float* xr  = x  + (size_t)src * Cc;
    const float* x1r = x1 + (size_t)src * Cc;

    float v0[6], v1[6];
    float s0 = 0.f, s1 = 0.f, q0 = 0.f, q1 = 0.f;
#pragma unroll
    for (int j = 0; j < 6; j++) {
        v0[j] = xr [lane + 32 * j];
        v1[j] = x1r[lane + 32 * j];
        s0 += v0[j]; q0 += v0[j] * v0[j];
        s1 += v1[j]; q1 += v1[j] * v1[j];
    }
#pragma unroll
    for (int o = 16; o > 0; o >>= 1) {
        s0 += __shfl_xor_sync(0xffffffffu, s0, o);
        q0 += __shfl_xor_sync(0xffffffffu, q0, o);
        s1 += __shfl_xor_sync(0xffffffffu, s1, o);
        q1 += __shfl_xor_sync(0xffffffffu, q1, o);
    }
    float mu0 = s0 * (1.f / Cc), mu1 = s1 * (1.f / Cc);
    float r0 = rsqrtf(q0 * (1.f / Cc) - mu0 * mu0 + 1e-5f);
    float r1 = rsqrtf(q1 * (1.f / Cc) - mu1 * mu1 + 1e-5f);
    size_t ob = (size_t)warp * Cc;
#pragma unroll
    for (int j = 0; j < 6; j++) {
        int e = lane + 32 * j;
        float ge = g[e], be = b[e];
        g_xw [ob + e] = (v0[j] - mu0) * r0 * ge + be;
        g_x1w[ob + e] = (v1[j] - mu1) * r1 * ge + be;
    }
}

// ---------------- LN2 ----------------
__global__ __launch_bounds__(256) void ln2_kernel(
    const float* __restrict__ xin,
    const float* __restrict__ g, const float* __restrict__ b)
{
    int warp = (blockIdx.x * blockDim.x + threadIdx.x) >> 5;
    int lane = threadIdx.x & 31;
    if (warp >= MTOK) return;
    const float* xr = xin + (size_t)warp * Cc;
    float v[6]; float s = 0.f, q = 0.f;
#pragma unroll
    for (int j = 0; j < 6; j++) {
        v[j] = xr[lane + 32 * j];
        s += v[j]; q += v[j] * v[j];
    }
#pragma unroll
    for (int o = 16; o > 0; o >>= 1) {
        s += __shfl_xor_sync(0xffffffffu, s, o);
        q += __shfl_xor_sync(0xffffffffu, q, o);
    }
    float mu = s * (1.f / Cc);
    float rs = rsqrtf(q * (1.f / Cc) - mu * mu + 1e-5f);
    size_t ob = (size_t)warp * Cc;
#pragma unroll
    for (int j = 0; j < 6; j++) {
        int e = lane + 32 * j;
        g_xn2[ob + e] = (v[j] - mu) * rs * g[e] + b[e];
    }
}

// ---------------- attention v4: mma.tf32 per (window, head) ----------
// block = 128 thr = 4 warps; warp w owns query rows [16w, 16w+16)
__device__ __forceinline__ int rel_idx(int n, int m) {
    return ((n >> 3) - (m >> 3) + 7) * 15 + ((n & 7) - (m & 7) + 7);
}

__global__ __launch_bounds__(128) void attn_kernel(
    const float* __restrict__ rpb_table, const float* __restrict__ mask)
{
    __shared__ uint32_t qs[64][36];
    __shared__ uint32_t ks[64][36];
    __shared__ uint32_t vs[64][36];
    __shared__ float    mask_s[64 * 66];
    __shared__ float    rpb_s[225];

    int bx   = blockIdx.x;
    int h    = bx % HEADS;
    int w    = bx / HEADS;          // window 0..2047
    int tid  = threadIdx.x;
    int lane = tid & 31;
    int warp = tid >> 5;
    int base = w * 64;

    const float scale = 0.17677669529663687f;

    // ---- stage Q (pre-scaled), K, V as tf32 ----
#pragma unroll
    for (int i = 0; i < 4; i++) {
        int idx = tid + i * 128;          // 0..511
        int row = idx >> 3;
        int c0  = (idx & 7) * 4;
        float4 fq = __ldg((const float4*)(g_q  + (size_t)(base + row) * Cc  + h * HD + c0));
        float4 fk = __ldg((const float4*)(g_kv + (size_t)(base + row) * 384 + h * HD + c0));
        float4 fv = __ldg((const float4*)(g_kv + (size_t)(base + row) * 384 + 192 + h * HD + c0));
        qs[row][c0 + 0] = f2tf32(fq.x * scale);
        qs[row][c0 + 1] = f2tf32(fq.y * scale);
        qs[row][c0 + 2] = f2tf32(fq.z * scale);
        qs[row][c0 + 3] = f2tf32(fq.w * scale);
        ks[row][c0 + 0] = f2tf32(fk.x);
        ks[row][c0 + 1] = f2tf32(fk.y);
        ks[row][c0 + 2] = f2tf32(fk.z);
        ks[row][c0 + 3] = f2tf32(fk.w);
        vs[row][c0 + 0] = f2tf32(fv.x);
        vs[row][c0 + 1] = f2tf32(fv.y);
        vs[row][c0 + 2] = f2tf32(fv.z);
        vs[row][c0 + 3] = f2tf32(fv.w);
    }
    // ---- stage mask (row stride 66 floats, float2-aligned) ----
    {
        const float* mb = mask + (size_t)(w & 511) * 4096;
#pragma unroll
        for (int i = 0; i < 16; i++) {
            int idx = tid + i * 128;       // 0..2047 float2 units
            int row = idx >> 5;
            int c   = (idx & 31) * 2;
            float2 f = __ldg((const float2*)(mb + row * 64 + c));
            mask_s[row * 66 + c]     = f.x;
            mask_s[row * 66 + c + 1] = f.y;
        }
    }
    // ---- stage rpb for this head ----
    for (int i = tid; i < 225; i += 128)
        rpb_s[i] = __ldg(rpb_table + i * HEADS + h);
    __syncthreads();

    int r  = lane >> 2;    // 0..7
    int q  = lane & 3;     // 0..3
    int n0 = warp * 16;

    // ---- S = Q @ K^T  (per warp: 16 x 64) ----
    float Sc[8][4];
#pragma unroll
    for (int nt = 0; nt < 8; nt++)
#pragma unroll
        for (int e = 0; e < 4; e++) Sc[nt][e] = 0.f;

#pragma unroll
    for (int kc = 0; kc < 4; kc++) {
        uint32_t a0 = qs[n0 + r    ][kc * 8 + q];
        uint32_t a1 = qs[n0 + r + 8][kc * 8 + q];
        uint32_t a2 = qs[n0 + r    ][kc * 8 + q + 4];
        uint32_t a3 = qs[n0 + r + 8][kc * 8 + q + 4];
#pragma unroll
        for (int nt = 0; nt < 8; nt++) {
            uint32_t b0 = ks[nt * 8 + r][kc * 8 + q];
            uint32_t b1 = ks[nt * 8 + r][kc * 8 + q + 4];
            asm volatile(
                "mma.sync.aligned.m16n8k8.row.col.f32.tf32.tf32.f32 "
                "{%0,%1,%2,%3},{%4,%5,%6,%7},{%8,%9},{%0,%1,%2,%3};"
                : "+f"(Sc[nt][0]), "+f"(Sc[nt][1]), "+f"(Sc[nt][2]), "+f"(Sc[nt][3])
                : "r"(a0), "r"(a1), "r"(a2), "r"(a3), "r"(b0), "r"(b1));
        }
    }

    // ---- bias + exp + row sums ----
    int nr0 = n0 + r, nr1 = n0 + r + 8;
    float sum0 = 0.f, sum1 = 0.f;
#pragma unroll
    for (int nt = 0; nt < 8; nt++) {
        int m0 = nt * 8 + 2 * q;
        int m1 = m0 + 1;
        Sc[nt][0] = __expf(Sc[nt][0] + rpb_s[rel_idx(nr0, m0)] + mask_s[nr0 * 66 + m0]);
        Sc[nt][1] = __expf(Sc[nt][1] + rpb_s[rel_idx(nr0, m1)] + mask_s[nr0 * 66 + m1]);
        Sc[nt][2] = __expf(Sc[nt][2] + rpb_s[rel_idx(nr1, m0)] + mask_s[nr1 * 66 + m0]);
        Sc[nt][3] = __expf(Sc[nt][3] + rpb_s[rel_idx(nr1, m1)] + mask_s[nr1 * 66 + m1]);
        sum0 += Sc[nt][0] + Sc[nt][1];
        sum1 += Sc[nt][2] + Sc[nt][3];
    }
    sum0 += __shfl_xor_sync(0xffffffffu, sum0, 1);
    sum0 += __shfl_xor_sync(0xffffffffu, sum0, 2);
    sum1 += __shfl_xor_sync(0xffffffffu, sum1, 1);
    sum1 += __shfl_xor_sync(0xffffffffu, sum1, 2);
    float inv0 = 1.f / sum0, inv1 = 1.f / sum1;

    // ---- convert P to tf32 ----
    uint32_t Pc[8][4];
#pragma unroll
    for (int nt = 0; nt < 8; nt++)
#pragma unroll
        for (int e = 0; e < 4; e++) Pc[nt][e] = f2tf32(Sc[nt][e]);

    // ---- O = P @ V  (16 x 32), P fragments via quad shuffles ----
    float Oc[4][4];
#pragma unroll
    for (int nt = 0; nt < 4; nt++)
#pragma unroll
        for (int e = 0; e < 4; e++) Oc[nt][e] = 0.f;

    int par  = q & 1;
    int src0 = (lane & ~3) | (q >> 1);
    int src1 = src0 + 2;

#pragma unroll
    for (int kt = 0; kt < 8; kt++) {
        uint32_t v00 = __shfl_sync(0xffffffffu, Pc[kt][0], src0);
        uint32_t v01 = __shfl_sync(0xffffffffu, Pc[kt][1], src0);
        uint32_t v20 = __shfl_sync(0xffffffffu, Pc[kt][2], src0);
        uint32_t v21 = __shfl_sync(0xffffffffu, Pc[kt][3], src0);
        uint32_t w00 = __shfl_sync(0xffffffffu, Pc[kt][0], src1);
        uint32_t w01 = __shfl_sync(0xffffffffu, Pc[kt][1], src1);
        uint32_t w20 = __shfl_sync(0xffffffffu, Pc[kt][2], src1);
        uint32_t w21 = __shfl_sync(0xffffffffu, Pc[kt][3], src1);
        uint32_t a0 = par ? v01 : v00;
        uint32_t a1 = par ? v21 : v20;
        uint32_t a2 = par ? w01 : w00;
        uint32_t a3 = par ? w21 : w20;
#pragma unroll
        for (int nt2 = 0; nt2 < 4; nt2++) {
            uint32_t b0 = vs[kt * 8 + q    ][nt2 * 8 + r];
            uint32_t b1 = vs[kt * 8 + q + 4][nt2 * 8 + r];
            asm volatile(
                "mma.sync.aligned.m16n8k8.row.col.f32.tf32.tf32.f32 "
                "{%0,%1,%2,%3},{%4,%5,%6,%7},{%8,%9},{%0,%1,%2,%3};"
                : "+f"(Oc[nt2][0]), "+f"(Oc[nt2][1]), "+f"(Oc[nt2][2]), "+f"(Oc[nt2][3])
                : "r"(a0), "r"(a1), "r"(a2), "r"(a3), "r"(b0), "r"(b1));
        }
    }

    // ---- writeback ----
#pragma unroll
    for (int nt2 = 0; nt2 < 4; nt2++) {
        float* p0 = g_ao + (size_t)(base + nr0) * Cc + h * HD + nt2 * 8 + 2 * q;
        float* p1 = g_ao + (size_t)(base + nr1) * Cc + h * HD + nt2 * 8 + 2 * q;
        *(float2*)p0 = make_float2(Oc[nt2][0] * inv0, Oc[nt2][1] * inv0);
        *(float2*)p1 = make_float2(Oc[nt2][2] * inv1, Oc[nt2][3] * inv1);
    }
}

// ---------------- tf32 GEMM, cp.async double-buffered ----------------
#define ASTR 36
#define BSTR 68

template <int EPI>
__global__ __launch_bounds__(256) void gemm_tf32_kernel(
    const float* __restrict__ A, const float* __restrict__ B,
    const float* __restrict__ bias, float* __restrict__ out,
    const float* __restrict__ src, int M, int N, int K)
{
    __shared__ float As[2][128][ASTR];
    __shared__ float Bs[2][32][BSTR];

    int tid  = threadIdx.x;
    int lane = tid & 31;
    int warp = tid >> 5;
    int warpm = warp >> 1;
    int warpn = warp & 1;
    int g   = lane >> 2;
    int tig = lane & 3;

    int bm = blockIdx.x, bn = blockIdx.y;

    float acc[2][4][4];
#pragma unroll
    for (int mi = 0; mi < 2; mi++)
#pragma unroll
        for (int ni = 0; ni < 4; ni++)
#pragma unroll
            for (int r = 0; r < 4; r++) acc[mi][ni][r] = 0.f;

    auto copy_tile = [&](int buf, int k0) {
#pragma unroll
        for (int i = 0; i < 4; i++) {
            int c   = tid + i * 256;
            int row = c >> 3;
            int kc  = (c & 7) * 4;
            const float* gp = A + (size_t)(bm * 128 + row) * K + k0 + kc;
            uint32_t dp = smem_u32(&As[buf][row][kc]);
            asm volatile("cp.async.ca.shared.global [%0], [%1], 16;" :: "r"(dp), "l"(gp));
        }
#pragma unroll
        for (int i = 0; i < 2; i++) {
            int c  = tid + i * 256;
            int kr = c >> 4;
            int nc = (c & 15) * 4;
            const float* gp = B + (size_t)(k0 + kr) * N + bn * 64 + nc;
            uint32_t dp = smem_u32(&Bs[buf][kr][nc]);
            asm volatile("cp.async.ca.shared.global [%0], [%1], 16;" :: "r"(dp), "l"(gp));
        }
        asm volatile("cp.async.commit_group;");
    };

    copy_tile(0, 0);

    int buf = 0;
    for (int k0 = 0; k0 < K; k0 += 32, buf ^= 1) {
        if (k0 + 32 < K) {
            copy_tile(buf ^ 1, k0 + 32);
            asm volatile("cp.async.wait_group 1;");
        } else {
            asm volatile("cp.async.wait_group 0;");
        }
        __syncthreads();

#pragma unroll
        for (int ks = 0; ks < 32; ks += 8) {
            uint32_t a[2][4], b[4][2];
#pragma unroll
            for (int mi = 0; mi < 2; mi++) {
                int mb = warpm * 32 + mi * 16;
                a[mi][0] = f2tf32(As[buf][mb + g    ][ks + tig]);
                a[mi][1] = f2tf32(As[buf][mb + g + 8][ks + tig]);
                a[mi][2] = f2tf32(As[buf][mb + g    ][ks + tig + 4]);
                a[mi][3] = f2tf32(As[buf][mb + g + 8][ks + tig + 4]);
            }
#pragma unroll
            for (int ni = 0; ni < 4; ni++) {
                int nb = warpn * 32 + ni * 8 + g;
                b[ni][0] = f2tf32(Bs[buf][ks + tig    ][nb]);
                b[ni][1] = f2tf32(Bs[buf][ks + tig + 4][nb]);
            }
#pragma unroll
            for (int mi = 0; mi < 2; mi++)
#pragma unroll
                for (int ni = 0; ni < 4; ni++) {
                    asm volatile(
                        "mma.sync.aligned.m16n8k8.row.col.f32.tf32.tf32.f32 "
                        "{%0,%1,%2,%3},{%4,%5,%6,%7},{%8,%9},{%0,%1,%2,%3};"
                        : "+f"(acc[mi][ni][0]), "+f"(acc[mi][ni][1]),
                          "+f"(acc[mi][ni][2]), "+f"(acc[mi][ni][3])
                        : "r"(a[mi][0]), "r"(a[mi][1]), "r"(a[mi][2]), "r"(a[mi][3]),
                          "r"(b[ni][0]), "r"(b[ni][1]));
                }
        }
        __syncthreads();
    }

#pragma unroll
    for (int mi = 0; mi < 2; mi++) {
#pragma unroll
        for (int ni = 0; ni < 4; ni++) {
            int r0 = bm * 128 + warpm * 32 + mi * 16 + g;
            int c  = bn * 64  + warpn * 32 + ni * 8 + tig * 2;
            float bia0 = bias[c], bia1 = bias[c + 1];
#pragma unroll
            for (int half = 0; half < 2; half++) {
                int r = r0 + half * 8;
                float v0 = acc[mi][ni][half * 2 + 0] + bia0;
                float v1 = acc[mi][ni][half * 2 + 1] + bia1;
                if (EPI == 0) {
                    *(float2*)(out + (size_t)r * N + c) = make_float2(v0, v1);
                } else if (EPI == 1) {
                    v0 = 0.5f * v0 * (1.f + erff(v0 * 0.7071067811865475f));
                    v1 = 0.5f * v1 * (1.f + erff(v1 * 0.7071067811865475f));
                    *(float2*)(out + (size_t)r * N + c) = make_float2(v0, v1);
                } else if (EPI == 2) {
                    int dr = map_row(r);
                    size_t o0 = (size_t)dr * Cc + c;
                    out[o0]     = src[o0]     + v0;
                    out[o0 + 1] = src[o0 + 1] + v1;
                } else {
                    size_t o0 = (size_t)r * N + c;
                    out[o0]     += v0;
                    out[o0 + 1] += v1;
                }
            }
        }
    }
}

// ---------------- launch ----------------
extern "C" void kernel_launch(void* const* d_in, const int* in_sizes, int n_in,
                              void* d_out, int out_size)
{
    (void)in_sizes; (void)n_in; (void)out_size;
    const float* x    = (const float*)d_in[0];
    const float* x1   = (const float*)d_in[1];
    const float* mask = (const float*)d_in[2];
    const float* n1g  = (const float*)d_in[3];
    const float* n1b  = (const float*)d_in[4];
    const float* qw   = (const float*)d_in[5];
    const float* qb   = (const float*)d_in[6];
    const float* kvw  = (const float*)d_in[7];
    const float* kvb  = (const float*)d_in[8];
    const float* rpb  = (const float*)d_in[9];
    const float* pw   = (const float*)d_in[10];
    const float* pb   = (const float*)d_in[11];
    const float* n2g  = (const float*)d_in[12];
    const float* n2b  = (const float*)d_in[13];
    const float* f1w  = (const float*)d_in[14];
    const float* f1b  = (const float*)d_in[15];
    const float* f2w  = (const float*)d_in[16];
    const float* f2b  = (const float*)d_in[17];
    float* out = (float*)d_out;

    float *xw, *x1w, *q, *kv, *ao, *xn2, *h;
    cudaGetSymbolAddress((void**)&xw,  g_xw);
    cudaGetSymbolAddress((void**)&x1w, g_x1w);
    cudaGetSymbolAddress((void**)&q,   g_q);
    cudaGetSymbolAddress((void**)&kv,  g_kv);
    cudaGetSymbolAddress((void**)&ao,  g_ao);
    cudaGetSymbolAddress((void**)&xn2, g_xn2);
    cudaGetSymbolAddress((void**)&h,   g_h);

    ln1_gather_kernel<<<MTOK / 8, 256>>>(x, x1, n1g, n1b);
    gemm_tf32_kernel<0><<<dim3(MTOK / 128, 6), 256>>>(xw, kvw, kvb, kv, nullptr, MTOK, 2 * Cc, Cc);
    gemm_tf32_kernel<0><<<dim3(MTOK / 128, 3), 256>>>(x1w, qw, qb, q, nullptr, MTOK, Cc, Cc);
    attn_kernel<<<BW * HEADS, 128>>>(rpb, mask);
    gemm_tf32_kernel<2><<<dim3(MTOK / 128, 3), 256>>>(ao, pw, pb, out, x, MTOK, Cc, Cc);
    ln2_kernel<<<MTOK / 8, 256>>>(out, n2g, n2b);
    gemm_tf32_kernel<1><<<dim3(MTOK / 128, 12), 256>>>(xn2, f1w, f1b, h, nullptr, MTOK, HID, Cc);
    gemm_tf32_kernel<3><<<dim3(MTOK / 128, 3), 256>>>(h, f2w, f2b, out, nullptr, MTOK, Cc, HID);
}

// round 5
// speedup vs baseline: 4.5521x; 1.6257x over previous
#include <cuda_runtime.h>
#include <cuda_bf16.h>
#include <math.h>
#include <stdint.h>

// ---------------- problem constants ----------------
#define Bz    4
#define Hh    128
#define Wfull 256
#define Cc    192
#define Ll    (Hh*Wfull)
#define HEADS 6
#define HD    32
#define NWIN  512
#define BW    (Bz*NWIN)         // 2048 windows
#define MTOK  (BW*64)           // 131072 window tokens
#define HID   768

typedef __nv_bfloat16 bf16;

// ---------------- scratch ----------------
__device__ bf16  g_xw [MTOK*Cc];
__device__ bf16  g_x1w[MTOK*Cc];
__device__ bf16  g_q  [MTOK*Cc];
__device__ bf16  g_kv [MTOK*2*Cc];
__device__ bf16  g_ao [MTOK*Cc];
__device__ bf16  g_xn2[MTOK*Cc];
__device__ bf16  g_h  [MTOK*HID];
// bf16 weights
__device__ bf16  g_qwb [Cc*Cc];
__device__ bf16  g_kvwb[Cc*2*Cc];
__device__ bf16  g_pwb [Cc*Cc];
__device__ bf16  g_f1wb[Cc*HID];
__device__ bf16  g_f2wb[HID*Cc];

__device__ __forceinline__ int map_row(int t) {
    int b_  = t >> 6;
    int n   = t & 63;
    int b   = b_ >> 9;
    int win = b_ & 511;
    int hi  = win >> 5;
    int wi  = win & 31;
    int r   = n >> 3, c = n & 7;
    int sh  = (hi * 8 + r + 4) & (Hh - 1);
    int sw  = (wi * 8 + c + 4) & (Wfull - 1);
    return b * Ll + sh * Wfull + sw;
}

__device__ __forceinline__ uint32_t smem_u32(const void* p) {
    return (uint32_t)__cvta_generic_to_shared(p);
}
__device__ __forceinline__ uint32_t packbf(float x, float y) {
    __nv_bfloat162 t = __floats2bfloat162_rn(x, y);
    return *reinterpret_cast<uint32_t*>(&t);
}
__device__ __forceinline__ void ldsm_x4(uint32_t& r0, uint32_t& r1, uint32_t& r2, uint32_t& r3, uint32_t a) {
    asm volatile("ldmatrix.sync.aligned.m8n8.x4.shared.b16 {%0,%1,%2,%3}, [%4];"
                 : "=r"(r0), "=r"(r1), "=r"(r2), "=r"(r3) : "r"(a));
}
__device__ __forceinline__ void ldsm_x4t(uint32_t& r0, uint32_t& r1, uint32_t& r2, uint32_t& r3, uint32_t a) {
    asm volatile("ldmatrix.sync.aligned.m8n8.x4.trans.shared.b16 {%0,%1,%2,%3}, [%4];"
                 : "=r"(r0), "=r"(r1), "=r"(r2), "=r"(r3) : "r"(a));
}
#define MMA_BF16(C, A0,A1,A2,A3, B0,B1) \
    asm volatile("mma.sync.aligned.m16n8k16.row.col.f32.bf16.bf16.f32 " \
        "{%0,%1,%2,%3},{%4,%5,%6,%7},{%8,%9},{%0,%1,%2,%3};" \
        : "+f"(C[0]), "+f"(C[1]), "+f"(C[2]), "+f"(C[3]) \
        : "r"(A0), "r"(A1), "r"(A2), "r"(A3), "r"(B0), "r"(B1))

// ---------------- weight fp32 -> bf16 ----------------
__global__ void cvt_kernel(const float* __restrict__ s, bf16* __restrict__ d, int n) {
    int i = blockIdx.x * 256 + threadIdx.x;
    if (i < n) d[i] = __float2bfloat16_rn(s[i]);
}

// ---------------- LN1 + roll + window partition (bf16 out) ----------
__global__ __launch_bounds__(256) void ln1_gather_kernel(
    const float* __restrict__ x, const float* __restrict__ x1,
    const float* __restrict__ g, const float* __restrict__ b)
{
    int warp = (blockIdx.x * blockDim.x + threadIdx.x) >> 5;
    int lane = threadIdx.x & 31;
    if (warp >= MTOK) return;
    int src = map_row(warp);
    const float* xr  = x  + (size_t)src * Cc;
    const float* x1r = x1 + (size_t)src * Cc;

    float v0[6], v1[6];
    float s0 = 0.f, s1 = 0.f, q0 = 0.f, q1 = 0.f;
#pragma unroll
    for (int j = 0; j < 6; j++) {
        v0[j] = xr [lane + 32 * j];
        v1[j] = x1r[lane + 32 * j];
        s0 += v0[j]; q0 += v0[j] * v0[j];
        s1 += v1[j]; q1 += v1[j] * v1[j];
    }
#pragma unroll
    for (int o = 16; o > 0; o >>= 1) {
        s0 += __shfl_xor_sync(0xffffffffu, s0, o);
        q0 += __shfl_xor_sync(0xffffffffu, q0, o);
        s1 += __shfl_xor_sync(0xffffffffu, s1, o);
        q1 += __shfl_xor_sync(0xffffffffu, q1, o);
    }
    float mu0 = s0 * (1.f / Cc), mu1 = s1 * (1.f / Cc);
    float r0 = rsqrtf(q0 * (1.f / Cc) - mu0 * mu0 + 1e-5f);
    float r1 = rsqrtf(q1 * (1.f / Cc) - mu1 * mu1 + 1e-5f);
    size_t ob = (size_t)warp * Cc;
#pragma unroll
    for (int j = 0; j < 6; j++) {
        int e = lane + 32 * j;
        float ge = g[e], be = b[e];
        g_xw [ob + e] = __float2bfloat16_rn((v0[j] - mu0) * r0 * ge + be);
        g_x1w[ob + e] = __float2bfloat16_rn((v1[j] - mu1) * r1 * ge + be);
    }
}

// ---------------- LN2 (bf16 out) ----------------
__global__ __launch_bounds__(256) void ln2_kernel(
    const float* __restrict__ xin,
    const float* __restrict__ g, const float* __restrict__ b)
{
    int warp = (blockIdx.x * blockDim.x + threadIdx.x) >> 5;
    int lane = threadIdx.x & 31;
    if (warp >= MTOK) return;
    const float* xr = xin + (size_t)warp * Cc;
    float v[6]; float s = 0.f, q = 0.f;
#pragma unroll
    for (int j = 0; j < 6; j++) {
        v[j] = xr[lane + 32 * j];
        s += v[j]; q += v[j] * v[j];
    }
#pragma unroll
    for (int o = 16; o > 0; o >>= 1) {
        s += __shfl_xor_sync(0xffffffffu, s, o);
        q += __shfl_xor_sync(0xffffffffu, q, o);
    }
    float mu = s * (1.f / Cc);
    float rs = rsqrtf(q * (1.f / Cc) - mu * mu + 1e-5f);
    size_t ob = (size_t)warp * Cc;
#pragma unroll
    for (int j = 0; j < 6; j++) {
        int e = lane + 32 * j;
        g_xn2[ob + e] = __float2bfloat16_rn((v[j] - mu) * rs * g[e] + b[e]);
    }
}

// ---------------- attention v5: bf16 mma per (window, head) ----------
__device__ __forceinline__ int rel_idx(int n, int m) {
    return ((n >> 3) - (m >> 3) + 7) * 15 + ((n & 7) - (m & 7) + 7);
}

__global__ __launch_bounds__(128) void attn_kernel(
    const float* __restrict__ rpb_table, const float* __restrict__ mask)
{
    __shared__ bf16  qs[64][40];
    __shared__ bf16  ks[64][40];
    __shared__ bf16  vs[64][40];
    __shared__ float mask_s[64 * 68];
    __shared__ float rpb_s[225];

    int bx   = blockIdx.x;
    int h    = bx % HEADS;
    int w    = bx / HEADS;
    int tid  = threadIdx.x;
    int lane = tid & 31;
    int warp = tid >> 5;
    int base = w * 64;

    // stage Q/K/V (bf16 copies) via cp.async
#pragma unroll
    for (int i = 0; i < 2; i++) {
        int c   = tid + i * 128;              // 0..255
        int row = c >> 2;
        int off = (c & 3) * 8;
        const bf16* gq = g_q  + (size_t)(base + row) * Cc  + h * HD + off;
        const bf16* gk = g_kv + (size_t)(base + row) * 384 + h * HD + off;
        const bf16* gv = g_kv + (size_t)(base + row) * 384 + 192 + h * HD + off;
        asm volatile("cp.async.ca.shared.global [%0], [%1], 16;" :: "r"(smem_u32(&qs[row][off])), "l"(gq));
        asm volatile("cp.async.ca.shared.global [%0], [%1], 16;" :: "r"(smem_u32(&ks[row][off])), "l"(gk));
        asm volatile("cp.async.ca.shared.global [%0], [%1], 16;" :: "r"(smem_u32(&vs[row][off])), "l"(gv));
    }
    // stage mask
    {
        const float* mb = mask + (size_t)(w & 511) * 4096;
#pragma unroll
        for (int i = 0; i < 8; i++) {
            int c   = tid + i * 128;           // 0..1023 16B chunks
            int row = c >> 4;
            int col = (c & 15) * 4;
            asm volatile("cp.async.ca.shared.global [%0], [%1], 16;"
                         :: "r"(smem_u32(&mask_s[row * 68 + col])), "l"(mb + row * 64 + col));
        }
    }
    asm volatile("cp.async.commit_group;");
    for (int i = tid; i < 225; i += 128)
        rpb_s[i] = __ldg(rpb_table + i * HEADS + h);
    asm volatile("cp.async.wait_group 0;");
    __syncthreads();

    int r  = lane >> 2;
    int q  = lane & 3;
    int n0 = warp * 16;

    // ---- S = Q @ K^T ----
    float Sc[8][4];
#pragma unroll
    for (int nt = 0; nt < 8; nt++)
#pragma unroll
        for (int e = 0; e < 4; e++) Sc[nt][e] = 0.f;

#pragma unroll
    for (int kc = 0; kc < 2; kc++) {
        uint32_t a0, a1, a2, a3;
        ldsm_x4(a0, a1, a2, a3, smem_u32(&qs[n0 + (lane & 15)][kc * 16 + (lane >> 4) * 8]));
#pragma unroll
        for (int p = 0; p < 4; p++) {
            uint32_t r0, r1, r2, r3;   // r0=b0(ntA) r1=b0(ntB) r2=b1(ntA) r3=b1(ntB)
            ldsm_x4(r0, r1, r2, r3, smem_u32(&ks[p * 16 + (lane & 15)][kc * 16 + (lane >> 4) * 8]));
            MMA_BF16(Sc[2 * p    ], a0, a1, a2, a3, r0, r2);
            MMA_BF16(Sc[2 * p + 1], a0, a1, a2, a3, r1, r3);
        }
    }

    // ---- scale + bias + exp + row sums ----
    const float scale = 0.17677669529663687f;
    int nr0 = n0 + r, nr1 = n0 + r + 8;
    float sum0 = 0.f, sum1 = 0.f;
#pragma unroll
    for (int nt = 0; nt < 8; nt++) {
        int m0 = nt * 8 + 2 * q;
        int m1 = m0 + 1;
        Sc[nt][0] = __expf(Sc[nt][0] * scale + rpb_s[rel_idx(nr0, m0)] + mask_s[nr0 * 68 + m0]);
        Sc[nt][1] = __expf(Sc[nt][1] * scale + rpb_s[rel_idx(nr0, m1)] + mask_s[nr0 * 68 + m1]);
        Sc[nt][2] = __expf(Sc[nt][2] * scale + rpb_s[rel_idx(nr1, m0)] + mask_s[nr1 * 68 + m0]);
        Sc[nt][3] = __expf(Sc[nt][3] * scale + rpb_s[rel_idx(nr1, m1)] + mask_s[nr1 * 68 + m1]);
        sum0 += Sc[nt][0] + Sc[nt][1];
        sum1 += Sc[nt][2] + Sc[nt][3];
    }
    sum0 += __shfl_xor_sync(0xffffffffu, sum0, 1);
    sum0 += __shfl_xor_sync(0xffffffffu, sum0, 2);
    sum1 += __shfl_xor_sync(0xffffffffu, sum1, 1);
    sum1 += __shfl_xor_sync(0xffffffffu, sum1, 2);
    float inv0 = 1.f / sum0, inv1 = 1.f / sum1;

    // ---- P (bf16 A-fragments, no shuffles needed for k16 layout) ----
    uint32_t Pa[4][4];
#pragma unroll
    for (int kt = 0; kt < 4; kt++) {
        Pa[kt][0] = packbf(Sc[2 * kt    ][0], Sc[2 * kt    ][1]);
        Pa[kt][1] = packbf(Sc[2 * kt    ][2], Sc[2 * kt    ][3]);
        Pa[kt][2] = packbf(Sc[2 * kt + 1][0], Sc[2 * kt + 1][1]);
        Pa[kt][3] = packbf(Sc[2 * kt + 1][2], Sc[2 * kt + 1][3]);
    }

    // ---- O = P @ V ----
    float Oc[4][4];
#pragma unroll
    for (int nt = 0; nt < 4; nt++)
#pragma unroll
        for (int e = 0; e < 4; e++) Oc[nt][e] = 0.f;

#pragma unroll
    for (int kt = 0; kt < 4; kt++) {
#pragma unroll
        for (int np = 0; np < 2; np++) {
            uint32_t b0, b1, b2, b3;   // b0,b1 = nt=2np ; b2,b3 = nt=2np+1
            ldsm_x4t(b0, b1, b2, b3, smem_u32(&vs[kt * 16 + (lane & 15)][np * 16 + (lane >> 4) * 8]));
            MMA_BF16(Oc[2 * np    ], Pa[kt][0], Pa[kt][1], Pa[kt][2], Pa[kt][3], b0, b1);
            MMA_BF16(Oc[2 * np + 1], Pa[kt][0], Pa[kt][1], Pa[kt][2], Pa[kt][3], b2, b3);
        }
    }

    // ---- writeback (bf16) ----
#pragma unroll
    for (int nt = 0; nt < 4; nt++) {
        int col = h * HD + nt * 8 + 2 * q;
        *(uint32_t*)(g_ao + (size_t)(base + nr0) * Cc + col) = packbf(Oc[nt][0] * inv0, Oc[nt][1] * inv0);
        *(uint32_t*)(g_ao + (size_t)(base + nr1) * Cc + col) = packbf(Oc[nt][2] * inv1, Oc[nt][3] * inv1);
    }
}

// ---------------- bf16 GEMM: 128x192 tile, 384 thr, k-chunk 32 -------
// EPI: 0 bf16 store, 1 GELU->bf16, 2 proj scatter fp32(+residual), 3 fp32 +=
#define AS_STR 40
#define BS_STR 200

template <int EPI>
__global__ __launch_bounds__(384) void gemm_bf16_kernel(
    const bf16* __restrict__ A, const bf16* __restrict__ B,
    const float* __restrict__ bias, void* __restrict__ outv,
    const float* __restrict__ src, int M, int N, int K)
{
    __shared__ bf16 As[2][128][AS_STR];
    __shared__ bf16 Bs[2][32][BS_STR];

    int tid   = threadIdx.x;
    int lane  = tid & 31;
    int warp  = tid >> 5;
    int warpm = warp & 3;          // 0..3 rows
    int warpn = warp >> 2;         // 0..2 col groups of 64
    int bm = blockIdx.x, bn = blockIdx.y;

    float acc[2][8][4];
#pragma unroll
    for (int mi = 0; mi < 2; mi++)
#pragma unroll
        for (int ni = 0; ni < 8; ni++)
#pragma unroll
            for (int e = 0; e < 4; e++) acc[mi][ni][e] = 0.f;

    auto copy_tile = [&](int buf, int k0) {
#pragma unroll
        for (int c = tid; c < 512; c += 384) {
            int row = c >> 2;
            int off = (c & 3) * 8;
            const bf16* gp = A + (size_t)(bm * 128 + row) * K + k0 + off;
            asm volatile("cp.async.ca.shared.global [%0], [%1], 16;"
                         :: "r"(smem_u32(&As[buf][row][off])), "l"(gp));
        }
#pragma unroll
        for (int c = tid; c < 768; c += 384) {
            int row = c / 24;
            int col = (c % 24) * 8;
            const bf16* gp = B + (size_t)(k0 + row) * N + bn * 192 + col;
            asm volatile("cp.async.ca.shared.global [%0], [%1], 16;"
                         :: "r"(smem_u32(&Bs[buf][row][col])), "l"(gp));
        }
        asm volatile("cp.async.commit_group;");
    };

    copy_tile(0, 0);

    int buf = 0;
    for (int k0 = 0; k0 < K; k0 += 32, buf ^= 1) {
        if (k0 + 32 < K) {
            copy_tile(buf ^ 1, k0 + 32);
            asm volatile("cp.async.wait_group 1;");
        } else {
            asm volatile("cp.async.wait_group 0;");
        }
        __syncthreads();

#pragma unroll
        for (int kc = 0; kc < 2; kc++) {
            uint32_t a[2][4];
#pragma unroll
            for (int mi = 0; mi < 2; mi++)
                ldsm_x4(a[mi][0], a[mi][1], a[mi][2], a[mi][3],
                        smem_u32(&As[buf][warpm * 32 + mi * 16 + (lane & 15)][kc * 16 + (lane >> 4) * 8]));
            uint32_t bf[8][2];
#pragma unroll
            for (int p = 0; p < 4; p++) {
                uint32_t r0, r1, r2, r3;
                ldsm_x4t(r0, r1, r2, r3,
                         smem_u32(&Bs[buf][kc * 16 + (lane & 15)][warpn * 64 + p * 16 + (lane >> 4) * 8]));
                bf[2 * p][0] = r0; bf[2 * p][1] = r1;
                bf[2 * p + 1][0] = r2; bf[2 * p + 1][1] = r3;
            }
#pragma unroll
            for (int mi = 0; mi < 2; mi++)
#pragma unroll
                for (int ni = 0; ni < 8; ni++)
                    MMA_BF16(acc[mi][ni], a[mi][0], a[mi][1], a[mi][2], a[mi][3],
                             bf[ni][0], bf[ni][1]);
        }
        __syncthreads();
    }

    int r  = lane >> 2;
    int q2 = (lane & 3) * 2;
#pragma unroll
    for (int mi = 0; mi < 2; mi++) {
        int row0 = bm * 128 + warpm * 32 + mi * 16 + r;
#pragma unroll
        for (int ni = 0; ni < 8; ni++) {
            int col = bn * 192 + warpn * 64 + ni * 8 + q2;
            float b0 = bias[col], b1 = bias[col + 1];
            float v0 = acc[mi][ni][0] + b0, v1 = acc[mi][ni][1] + b1;
            float v2 = acc[mi][ni][2] + b0, v3 = acc[mi][ni][3] + b1;
            if (EPI == 0) {
                bf16* o = (bf16*)outv;
                *(uint32_t*)(o + (size_t)row0 * N + col)       = packbf(v0, v1);
                *(uint32_t*)(o + (size_t)(row0 + 8) * N + col) = packbf(v2, v3);
            } else if (EPI == 1) {
                bf16* o = (bf16*)outv;
                v0 = 0.5f * v0 * (1.f + erff(v0 * 0.7071067811865475f));
                v1 = 0.5f * v1 * (1.f + erff(v1 * 0.7071067811865475f));
                v2 = 0.5f * v2 * (1.f + erff(v2 * 0.7071067811865475f));
                v3 = 0.5f * v3 * (1.f + erff(v3 * 0.7071067811865475f));
                *(uint32_t*)(o + (size_t)row0 * N + col)       = packbf(v0, v1);
                *(uint32_t*)(o + (size_t)(row0 + 8) * N + col) = packbf(v2, v3);
            } else if (EPI == 2) {
                float* o = (float*)outv;
                int dr0 = map_row(row0), dr1 = map_row(row0 + 8);
                size_t o0 = (size_t)dr0 * Cc + col, o1 = (size_t)dr1 * Cc + col;
                *(float2*)(o + o0) = make_float2(src[o0] + v0, src[o0 + 1] + v1);
                *(float2*)(o + o1) = make_float2(src[o1] + v2, src[o1 + 1] + v3);
            } else {
                float* o = (float*)outv;
                size_t o0 = (size_t)row0 * N + col, o1 = (size_t)(row0 + 8) * N + col;
                o[o0] += v0; o[o0 + 1] += v1;
                o[o1] += v2; o[o1 + 1] += v3;
            }
        }
    }
}

// ---------------- launch ----------------
extern "C" void kernel_launch(void* const* d_in, const int* in_sizes, int n_in,
                              void* d_out, int out_size)
{
    (void)in_sizes; (void)n_in; (void)out_size;
    const float* x    = (const float*)d_in[0];
    const float* x1   = (const float*)d_in[1];
    const float* mask = (const float*)d_in[2];
    const float* n1g  = (const float*)d_in[3];
    const float* n1b  = (const float*)d_in[4];
    const float* qw   = (const float*)d_in[5];
    const float* qb   = (const float*)d_in[6];
    const float* kvw  = (const float*)d_in[7];
    const float* kvb  = (const float*)d_in[8];
    const float* rpb  = (const float*)d_in[9];
    const float* pw   = (const float*)d_in[10];
    const float* pb   = (const float*)d_in[11];
    const float* n2g  = (const float*)d_in[12];
    const float* n2b  = (const float*)d_in[13];
    const float* f1w  = (const float*)d_in[14];
    const float* f1b  = (const float*)d_in[15];
    const float* f2w  = (const float*)d_in[16];
    const float* f2b  = (const float*)d_in[17];
    float* out = (float*)d_out;

    bf16 *xw, *x1w, *q, *kv, *ao, *xn2, *h;
    bf16 *qwb, *kvwb, *pwb, *f1wb, *f2wb;
    cudaGetSymbolAddress((void**)&xw,  g_xw);
    cudaGetSymbolAddress((void**)&x1w, g_x1w);
    cudaGetSymbolAddress((void**)&q,   g_q);
    cudaGetSymbolAddress((void**)&kv,  g_kv);
    cudaGetSymbolAddress((void**)&ao,  g_ao);
    cudaGetSymbolAddress((void**)&xn2, g_xn2);
    cudaGetSymbolAddress((void**)&h,   g_h);
    cudaGetSymbolAddress((void**)&qwb,  g_qwb);
    cudaGetSymbolAddress((void**)&kvwb, g_kvwb);
    cudaGetSymbolAddress((void**)&pwb,  g_pwb);
    cudaGetSymbolAddress((void**)&f1wb, g_f1wb);
    cudaGetSymbolAddress((void**)&f2wb, g_f2wb);

    // weight conversions (tiny)
    cvt_kernel<<<(Cc*Cc + 255)/256, 256>>>(qw,  qwb,  Cc*Cc);
    cvt_kernel<<<(Cc*2*Cc + 255)/256, 256>>>(kvw, kvwb, Cc*2*Cc);
    cvt_kernel<<<(Cc*Cc + 255)/256, 256>>>(pw,  pwb,  Cc*Cc);
    cvt_kernel<<<(Cc*HID + 255)/256, 256>>>(f1w, f1wb, Cc*HID);
    cvt_kernel<<<(HID*Cc + 255)/256, 256>>>(f2w, f2wb, HID*Cc);

    ln1_gather_kernel<<<MTOK / 8, 256>>>(x, x1, n1g, n1b);
    gemm_bf16_kernel<0><<<dim3(MTOK / 128, 2), 384>>>(xw,  kvwb, kvb, kv, nullptr, MTOK, 2 * Cc, Cc);
    gemm_bf16_kernel<0><<<dim3(MTOK / 128, 1), 384>>>(x1w, qwb,  qb,  q,  nullptr, MTOK, Cc, Cc);
    attn_kernel<<<BW * HEADS, 128>>>(rpb, mask);
    gemm_bf16_kernel<2><<<dim3(MTOK / 128, 1), 384>>>(ao, pwb, pb, out, x, MTOK, Cc, Cc);
    ln2_kernel<<<MTOK / 8, 256>>>(out, n2g, n2b);
    gemm_bf16_kernel<1><<<dim3(MTOK / 128, 4), 384>>>(xn2, f1wb, f1b, h, nullptr, MTOK, HID, Cc);
    gemm_bf16_kernel<3><<<dim3(MTOK / 128, 1), 384>>>(h, f2wb, f2b, out, nullptr, MTOK, Cc, HID);
}

// round 6
// speedup vs baseline: 4.9984x; 1.0981x over previous
#include <cuda_runtime.h>
#include <cuda_bf16.h>
#include <math.h>
#include <stdint.h>

// ---------------- problem constants ----------------
#define Bz    4
#define Hh    128
#define Wfull 256
#define Cc    192
#define Ll    (Hh*Wfull)
#define HEADS 6
#define HD    32
#define NWIN  512
#define BW    (Bz*NWIN)         // 2048 windows
#define MTOK  (BW*64)           // 131072 window tokens
#define HID   768

typedef __nv_bfloat16 bf16;

// ---------------- scratch ----------------
__device__ bf16  g_xw [MTOK*Cc];
__device__ bf16  g_x1w[MTOK*Cc];
__device__ bf16  g_q  [MTOK*Cc];
__device__ bf16  g_kv [MTOK*2*Cc];
__device__ bf16  g_ao [MTOK*Cc];
__device__ bf16  g_h  [MTOK*HID];
// bf16 weights
__device__ bf16  g_qwb [Cc*Cc];
__device__ bf16  g_kvwb[Cc*2*Cc];
__device__ bf16  g_pwb [Cc*Cc];
__device__ bf16  g_f1wb[Cc*HID];
__device__ bf16  g_f2wb[HID*Cc];

__device__ __forceinline__ int map_row(int t) {
    int b_  = t >> 6;
    int n   = t & 63;
    int b   = b_ >> 9;
    int win = b_ & 511;
    int hi  = win >> 5;
    int wi  = win & 31;
    int r   = n >> 3, c = n & 7;
    int sh  = (hi * 8 + r + 4) & (Hh - 1);
    int sw  = (wi * 8 + c + 4) & (Wfull - 1);
    return b * Ll + sh * Wfull + sw;
}

__device__ __forceinline__ uint32_t smem_u32(const void* p) {
    return (uint32_t)__cvta_generic_to_shared(p);
}
__device__ __forceinline__ uint32_t packbf(float x, float y) {
    __nv_bfloat162 t = __floats2bfloat162_rn(x, y);
    return *reinterpret_cast<uint32_t*>(&t);
}
__device__ __forceinline__ void ldsm_x4(uint32_t& r0, uint32_t& r1, uint32_t& r2, uint32_t& r3, uint32_t a) {
    asm volatile("ldmatrix.sync.aligned.m8n8.x4.shared.b16 {%0,%1,%2,%3}, [%4];"
                 : "=r"(r0), "=r"(r1), "=r"(r2), "=r"(r3) : "r"(a));
}
__device__ __forceinline__ void ldsm_x4t(uint32_t& r0, uint32_t& r1, uint32_t& r2, uint32_t& r3, uint32_t a) {
    asm volatile("ldmatrix.sync.aligned.m8n8.x4.trans.shared.b16 {%0,%1,%2,%3}, [%4];"
                 : "=r"(r0), "=r"(r1), "=r"(r2), "=r"(r3) : "r"(a));
}
#define MMA_BF16(C, A0,A1,A2,A3, B0,B1) \
    asm volatile("mma.sync.aligned.m16n8k16.row.col.f32.bf16.bf16.f32 " \
        "{%0,%1,%2,%3},{%4,%5,%6,%7},{%8,%9},{%0,%1,%2,%3};" \
        : "+f"(C[0]), "+f"(C[1]), "+f"(C[2]), "+f"(C[3]) \
        : "r"(A0), "r"(A1), "r"(A2), "r"(A3), "r"(B0), "r"(B1))

// ---------------- all weights fp32 -> bf16, one launch ----------------
#define W1 (Cc*Cc)
#define W2 (W1 + Cc*2*Cc)
#define W3 (W2 + Cc*Cc)
#define W4 (W3 + Cc*HID)
#define W5 (W4 + HID*Cc)
__global__ void cvt_all_kernel(const float* __restrict__ qw, const float* __restrict__ kvw,
                               const float* __restrict__ pw, const float* __restrict__ f1w,
                               const float* __restrict__ f2w) {
    int i = blockIdx.x * 256 + threadIdx.x;
    if (i < W1)      g_qwb [i]      = __float2bfloat16_rn(qw [i]);
    else if (i < W2) g_kvwb[i - W1] = __float2bfloat16_rn(kvw[i - W1]);
    else if (i < W3) g_pwb [i - W2] = __float2bfloat16_rn(pw [i - W2]);
    else if (i < W4) g_f1wb[i - W3] = __float2bfloat16_rn(f1w[i - W3]);
    else if (i < W5) g_f2wb[i - W4] = __float2bfloat16_rn(f2w[i - W4]);
}

// ---------------- LN1 + roll + window partition (bf16 out) ----------
__global__ __launch_bounds__(256) void ln1_gather_kernel(
    const float* __restrict__ x, const float* __restrict__ x1,
    const float* __restrict__ g, const float* __restrict__ b)
{
    int warp = (blockIdx.x * blockDim.x + threadIdx.x) >> 5;
    int lane = threadIdx.x & 31;
    if (warp >= MTOK) return;
    int src = map_row(warp);
    const float* xr  = x  + (size_t)src * Cc;
    const float* x1r = x1 + (size_t)src * Cc;

    float v0[6], v1[6];
    float s0 = 0.f, s1 = 0.f, q0 = 0.f, q1 = 0.f;
#pragma unroll
    for (int j = 0; j < 6; j++) {
        v0[j] = xr [lane + 32 * j];
        v1[j] = x1r[lane + 32 * j];
        s0 += v0[j]; q0 += v0[j] * v0[j];
        s1 += v1[j]; q1 += v1[j] * v1[j];
    }
#pragma unroll
    for (int o = 16; o > 0; o >>= 1) {
        s0 += __shfl_xor_sync(0xffffffffu, s0, o);
        q0 += __shfl_xor_sync(0xffffffffu, q0, o);
        s1 += __shfl_xor_sync(0xffffffffu, s1, o);
        q1 += __shfl_xor_sync(0xffffffffu, q1, o);
    }
    float mu0 = s0 * (1.f / Cc), mu1 = s1 * (1.f / Cc);
    float r0 = rsqrtf(q0 * (1.f / Cc) - mu0 * mu0 + 1e-5f);
    float r1 = rsqrtf(q1 * (1.f / Cc) - mu1 * mu1 + 1e-5f);
    size_t ob = (size_t)warp * Cc;
#pragma unroll
    for (int j = 0; j < 6; j++) {
        int e = lane + 32 * j;
        float ge = g[e], be = b[e];
        g_xw [ob + e] = __float2bfloat16_rn((v0[j] - mu0) * r0 * ge + be);
        g_x1w[ob + e] = __float2bfloat16_rn((v1[j] - mu1) * r1 * ge + be);
    }
}

// ---------------- attention v6: bf16 mma, analytic mask --------------
__device__ __forceinline__ int rel_idx(int n, int m) {
    return ((n >> 3) - (m >> 3) + 7) * 15 + ((n & 7) - (m & 7) + 7);
}

__global__ __launch_bounds__(128) void attn_kernel(const float* __restrict__ rpb_table)
{
    __shared__ bf16  qs[64][40];
    __shared__ bf16  ks[64][40];
    __shared__ bf16  vs[64][40];
    __shared__ float rpb_s[225];

    int bx   = blockIdx.x;
    int h    = bx % HEADS;
    int w    = bx / HEADS;
    int tid  = threadIdx.x;
    int lane = tid & 31;
    int warp = tid >> 5;
    int base = w * 64;

    int fH = (((w >> 5) & 15) == 15) ? 1 : 0;
    int fW = ((w & 31) == 31) ? 1 : 0;

    // stage Q/K/V (bf16) via cp.async
#pragma unroll
    for (int i = 0; i < 2; i++) {
        int c   = tid + i * 128;
        int row = c >> 2;
        int off = (c & 3) * 8;
        const bf16* gq = g_q  + (size_t)(base + row) * Cc  + h * HD + off;
        const bf16* gk = g_kv + (size_t)(base + row) * 384 + h * HD + off;
        const bf16* gv = g_kv + (size_t)(base + row) * 384 + 192 + h * HD + off;
        asm volatile("cp.async.ca.shared.global [%0], [%1], 16;" :: "r"(smem_u32(&qs[row][off])), "l"(gq));
        asm volatile("cp.async.ca.shared.global [%0], [%1], 16;" :: "r"(smem_u32(&ks[row][off])), "l"(gk));
        asm volatile("cp.async.ca.shared.global [%0], [%1], 16;" :: "r"(smem_u32(&vs[row][off])), "l"(gv));
    }
    asm volatile("cp.async.commit_group;");
    for (int i = tid; i < 225; i += 128)
        rpb_s[i] = __ldg(rpb_table + i * HEADS + h);
    asm volatile("cp.async.wait_group 0;");
    __syncthreads();

    int r  = lane >> 2;
    int q  = lane & 3;
    int n0 = warp * 16;

    // ---- S = Q @ K^T ----
    float Sc[8][4];
#pragma unroll
    for (int nt = 0; nt < 8; nt++)
#pragma unroll
        for (int e = 0; e < 4; e++) Sc[nt][e] = 0.f;

#pragma unroll
    for (int kc = 0; kc < 2; kc++) {
        uint32_t a0, a1, a2, a3;
        ldsm_x4(a0, a1, a2, a3, smem_u32(&qs[n0 + (lane & 15)][kc * 16 + (lane >> 4) * 8]));
#pragma unroll
        for (int p = 0; p < 4; p++) {
            uint32_t r0, r1, r2, r3;
            ldsm_x4(r0, r1, r2, r3, smem_u32(&ks[p * 16 + (lane & 15)][kc * 16 + (lane >> 4) * 8]));
            MMA_BF16(Sc[2 * p    ], a0, a1, a2, a3, r0, r2);
            MMA_BF16(Sc[2 * p + 1], a0, a1, a2, a3, r1, r3);
        }
    }

    // ---- scale + rpb + analytic mask + exp + row sums ----
    const float scale = 0.17677669529663687f;
    int nr0 = n0 + r, nr1 = n0 + r + 8;
    int hq0 = (nr0 >= 32) ? 1 : 0, hq1 = (nr1 >= 32) ? 1 : 0;
    int wq  = (nr0 >> 2) & 1;                 // same for nr1
    int wm  = (q >= 2) ? 1 : 0;               // key col group for this thread's pair
    float sum0 = 0.f, sum1 = 0.f;
#pragma unroll
    for (int nt = 0; nt < 8; nt++) {
        int m0 = nt * 8 + 2 * q;
        int m1 = m0 + 1;
        int hm = (nt >= 4) ? 1 : 0;
        float pen0 = -100.f * (float)((fH & (hq0 ^ hm)) | (fW & (wq ^ wm)));
        float pen1 = -100.f * (float)((fH & (hq1 ^ hm)) | (fW & (wq ^ wm)));
        Sc[nt][0] = __expf(Sc[nt][0] * scale + rpb_s[rel_idx(nr0, m0)] + pen0);
        Sc[nt][1] = __expf(Sc[nt][1] * scale + rpb_s[rel_idx(nr0, m1)] + pen0);
        Sc[nt][2] = __expf(Sc[nt][2] * scale + rpb_s[rel_idx(nr1, m0)] + pen1);
        Sc[nt][3] = __expf(Sc[nt][3] * scale + rpb_s[rel_idx(nr1, m1)] + pen1);
        sum0 += Sc[nt][0] + Sc[nt][1];
        sum1 += Sc[nt][2] + Sc[nt][3];
    }
    sum0 += __shfl_xor_sync(0xffffffffu, sum0, 1);
    sum0 += __shfl_xor_sync(0xffffffffu, sum0, 2);
    sum1 += __shfl_xor_sync(0xffffffffu, sum1, 1);
    sum1 += __shfl_xor_sync(0xffffffffu, sum1, 2);
    float inv0 = 1.f / sum0, inv1 = 1.f / sum1;

    // ---- P bf16 A-fragments ----
    uint32_t Pa[4][4];
#pragma unroll
    for (int kt = 0; kt < 4; kt++) {
        Pa[kt][0] = packbf(Sc[2 * kt    ][0], Sc[2 * kt    ][1]);
        Pa[kt][1] = packbf(Sc[2 * kt    ][2], Sc[2 * kt    ][3]);
        Pa[kt][2] = packbf(Sc[2 * kt + 1][0], Sc[2 * kt + 1][1]);
        Pa[kt][3] = packbf(Sc[2 * kt + 1][2], Sc[2 * kt + 1][3]);
    }

    // ---- O = P @ V ----
    float Oc[4][4];
#pragma unroll
    for (int nt = 0; nt < 4; nt++)
#pragma unroll
        for (int e = 0; e < 4; e++) Oc[nt][e] = 0.f;

#pragma unroll
    for (int kt = 0; kt < 4; kt++) {
#pragma unroll
        for (int np = 0; np < 2; np++) {
            uint32_t b0, b1, b2, b3;
            ldsm_x4t(b0, b1, b2, b3, smem_u32(&vs[kt * 16 + (lane & 15)][np * 16 + (lane >> 4) * 8]));
            MMA_BF16(Oc[2 * np    ], Pa[kt][0], Pa[kt][1], Pa[kt][2], Pa[kt][3], b0, b1);
            MMA_BF16(Oc[2 * np + 1], Pa[kt][0], Pa[kt][1], Pa[kt][2], Pa[kt][3], b2, b3);
        }
    }

    // ---- writeback ----
#pragma unroll
    for (int nt = 0; nt < 4; nt++) {
        int col = h * HD + nt * 8 + 2 * q;
        *(uint32_t*)(g_ao + (size_t)(base + nr0) * Cc + col) = packbf(Oc[nt][0] * inv0, Oc[nt][1] * inv0);
        *(uint32_t*)(g_ao + (size_t)(base + nr1) * Cc + col) = packbf(Oc[nt][2] * inv1, Oc[nt][3] * inv1);
    }
}

// ---------------- A-stationary bf16 GEMM for K=192 -------------------
// Tile M=128, full K in smem; loops N in chunks of 192. 384 thr, 12 warps.
// LNA: A is fp32, apply LayerNorm during staging.
// EPI: 0 bf16 store, 1 GELU->bf16, 2 proj scatter fp32 (+residual)
#define GSM_BYTES (128*200*2 + 2*32*200*2)   // 76800

template <int EPI, bool LNA>
__global__ __launch_bounds__(384) void gemm192_kernel(
    const void* __restrict__ Ain, const bf16* __restrict__ Bw,
    const float* __restrict__ bias, void* __restrict__ outv,
    const float* __restrict__ src, const float* __restrict__ lng,
    const float* __restrict__ lnb, int N)
{
    extern __shared__ char smraw[];
    bf16 (*As)[200]      = reinterpret_cast<bf16(*)[200]>(smraw);
    bf16 (*Bs)[32][200]  = reinterpret_cast<bf16(*)[32][200]>(smraw + 128 * 200 * 2);

    int tid   = threadIdx.x;
    int lane  = tid & 31;
    int warp  = tid >> 5;
    int warpm = warp & 3;
    int warpn = warp >> 2;
    int bm    = blockIdx.x;

    auto copyB = [&](int buf, int nb, int s) {
#pragma unroll
        for (int c = tid; c < 768; c += 384) {
            int row = c / 24;
            int off = (c % 24) * 8;
            const bf16* gp = Bw + (size_t)(s * 32 + row) * N + nb * 192 + off;
            asm volatile("cp.async.ca.shared.global [%0], [%1], 16;"
                         :: "r"(smem_u32(&Bs[buf][row][off])), "l"(gp));
        }
        asm volatile("cp.async.commit_group;");
    };

    // prefetch first B slice
    copyB(0, 0, 0);

    // ---- stage A (full 128 x 192) ----
    if (LNA) {
        const float* A = (const float*)Ain;
        for (int i = warp; i < 128; i += 12) {
            const float* xr = A + (size_t)(bm * 128 + i) * Cc;
            float v[6]; float s = 0.f, qq = 0.f;
#pragma unroll
            for (int j = 0; j < 6; j++) {
                v[j] = xr[lane + 32 * j];
                s += v[j]; qq += v[j] * v[j];
            }
#pragma unroll
            for (int o = 16; o > 0; o >>= 1) {
                s  += __shfl_xor_sync(0xffffffffu, s,  o);
                qq += __shfl_xor_sync(0xffffffffu, qq, o);
            }
            float mu = s * (1.f / Cc);
            float rs = rsqrtf(qq * (1.f / Cc) - mu * mu + 1e-5f);
#pragma unroll
            for (int j = 0; j < 6; j++) {
                int e = lane + 32 * j;
                As[i][e] = __float2bfloat16_rn((v[j] - mu) * rs * lng[e] + lnb[e]);
            }
        }
    } else {
        const bf16* A = (const bf16*)Ain;
#pragma unroll
        for (int c = tid; c < 3072; c += 384) {
            int row = c / 24;
            int off = (c % 24) * 8;
            const bf16* gp = A + (size_t)(bm * 128 + row) * Cc + off;
            asm volatile("cp.async.ca.shared.global [%0], [%1], 16;"
                         :: "r"(smem_u32(&As[row][off])), "l"(gp));
        }
        asm volatile("cp.async.commit_group;");
    }

    int r  = lane >> 2;
    int q2 = (lane & 3) * 2;
    int nchunks = N / 192;

    for (int nb = 0; nb < nchunks; nb++) {
        if (nb > 0) copyB(0, nb, 0);

        float acc[2][8][4];
#pragma unroll
        for (int mi = 0; mi < 2; mi++)
#pragma unroll
            for (int ni = 0; ni < 8; ni++)
#pragma unroll
                for (int e = 0; e < 4; e++) acc[mi][ni][e] = 0.f;

        int buf = 0;
#pragma unroll
        for (int s = 0; s < 6; s++) {
            if (s < 5) {
                copyB(buf ^ 1, nb, s + 1);
                asm volatile("cp.async.wait_group 1;");
            } else {
                asm volatile("cp.async.wait_group 0;");
            }
            __syncthreads();

#pragma unroll
            for (int kc = 0; kc < 2; kc++) {
                uint32_t a[2][4];
#pragma unroll
                for (int mi = 0; mi < 2; mi++)
                    ldsm_x4(a[mi][0], a[mi][1], a[mi][2], a[mi][3],
                            smem_u32(&As[warpm * 32 + mi * 16 + (lane & 15)][s * 32 + kc * 16 + (lane >> 4) * 8]));
                uint32_t bf[8][2];
#pragma unroll
                for (int p = 0; p < 4; p++) {
                    uint32_t r0, r1, r2, r3;
                    ldsm_x4t(r0, r1, r2, r3,
                             smem_u32(&Bs[buf][kc * 16 + (lane & 15)][warpn * 64 + p * 16 + (lane >> 4) * 8]));
                    bf[2 * p][0] = r0; bf[2 * p][1] = r1;
                    bf[2 * p + 1][0] = r2; bf[2 * p + 1][1] = r3;
                }
#pragma unroll
                for (int mi = 0; mi < 2; mi++)
#pragma unroll
                    for (int ni = 0; ni < 8; ni++)
                        MMA_BF16(acc[mi][ni], a[mi][0], a[mi][1], a[mi][2], a[mi][3],
                                 bf[ni][0], bf[ni][1]);
            }
            __syncthreads();
            buf ^= 1;
        }

        // ---- epilogue for this N-chunk ----
#pragma unroll
        for (int mi = 0; mi < 2; mi++) {
            int row0 = bm * 128 + warpm * 32 + mi * 16 + r;
#pragma unroll
            for (int ni = 0; ni < 8; ni++) {
                int col = nb * 192 + warpn * 64 + ni * 8 + q2;
                float b0 = bias[col], b1 = bias[col + 1];
                float v0 = acc[mi][ni][0] + b0, v1 = acc[mi][ni][1] + b1;
                float v2 = acc[mi][ni][2] + b0, v3 = acc[mi][ni][3] + b1;
                if (EPI == 0) {
                    bf16* o = (bf16*)outv;
                    *(uint32_t*)(o + (size_t)row0 * N + col)       = packbf(v0, v1);
                    *(uint32_t*)(o + (size_t)(row0 + 8) * N + col) = packbf(v2, v3);
                } else if (EPI == 1) {
                    bf16* o = (bf16*)outv;
                    v0 = 0.5f * v0 * (1.f + erff(v0 * 0.7071067811865475f));
                    v1 = 0.5f * v1 * (1.f + erff(v1 * 0.7071067811865475f));
                    v2 = 0.5f * v2 * (1.f + erff(v2 * 0.7071067811865475f));
                    v3 = 0.5f * v3 * (1.f + erff(v3 * 0.7071067811865475f));
                    *(uint32_t*)(o + (size_t)row0 * N + col)       = packbf(v0, v1);
                    *(uint32_t*)(o + (size_t)(row0 + 8) * N + col) = packbf(v2, v3);
                } else {
                    float* o = (float*)outv;
                    int dr0 = map_row(row0), dr1 = map_row(row0 + 8);
                    size_t o0 = (size_t)dr0 * Cc + col, o1 = (size_t)dr1 * Cc + col;
                    *(float2*)(o + o0) = make_float2(src[o0] + v0, src[o0 + 1] + v1);
                    *(float2*)(o + o1) = make_float2(src[o1] + v2, src[o1 + 1] + v3);
                }
            }
        }
    }
}

// ---------------- streaming bf16 GEMM (fc2, K=768) -------------------
#define AS_STR 40
#define BS_STR 200

__global__ __launch_bounds__(384) void gemm_fc2_kernel(
    const bf16* __restrict__ A, const bf16* __restrict__ B,
    const float* __restrict__ bias, float* __restrict__ out,
    int M, int N, int K)
{
    __shared__ bf16 As[2][128][AS_STR];
    __shared__ bf16 Bs[2][32][BS_STR];

    int tid   = threadIdx.x;
    int lane  = tid & 31;
    int warp  = tid >> 5;
    int warpm = warp & 3;
    int warpn = warp >> 2;
    int bm = blockIdx.x;

    float acc[2][8][4];
#pragma unroll
    for (int mi = 0; mi < 2; mi++)
#pragma unroll
        for (int ni = 0; ni < 8; ni++)
#pragma unroll
            for (int e = 0; e < 4; e++) acc[mi][ni][e] = 0.f;

    auto copy_tile = [&](int buf, int k0) {
#pragma unroll
        for (int c = tid; c < 512; c += 384) {
            int row = c >> 2;
            int off = (c & 3) * 8;
            const bf16* gp = A + (size_t)(bm * 128 + row) * K + k0 + off;
            asm volatile("cp.async.ca.shared.global [%0], [%1], 16;"
                         :: "r"(smem_u32(&As[buf][row][off])), "l"(gp));
        }
#pragma unroll
        for (int c = tid; c < 768; c += 384) {
            int row = c / 24;
            int col = (c % 24) * 8;
            const bf16* gp = B + (size_t)(k0 + row) * N + col;
            asm volatile("cp.async.ca.shared.global [%0], [%1], 16;"
                         :: "r"(smem_u32(&Bs[buf][row][col])), "l"(gp));
        }
        asm volatile("cp.async.commit_group;");
    };

    copy_tile(0, 0);

    int buf = 0;
    for (int k0 = 0; k0 < K; k0 += 32, buf ^= 1) {
        if (k0 + 32 < K) {
            copy_tile(buf ^ 1, k0 + 32);
            asm volatile("cp.async.wait_group 1;");
        } else {
            asm volatile("cp.async.wait_group 0;");
        }
        __syncthreads();

#pragma unroll
        for (int kc = 0; kc < 2; kc++) {
            uint32_t a[2][4];
#pragma unroll
            for (int mi = 0; mi < 2; mi++)
                ldsm_x4(a[mi][0], a[mi][1], a[mi][2], a[mi][3],
                        smem_u32(&As[buf][warpm * 32 + mi * 16 + (lane & 15)][kc * 16 + (lane >> 4) * 8]));
            uint32_t bf[8][2];
#pragma unroll
            for (int p = 0; p < 4; p++) {
                uint32_t r0, r1, r2, r3;
                ldsm_x4t(r0, r1, r2, r3,
                         smem_u32(&Bs[buf][kc * 16 + (lane & 15)][warpn * 64 + p * 16 + (lane >> 4) * 8]));
                bf[2 * p][0] = r0; bf[2 * p][1] = r1;
                bf[2 * p + 1][0] = r2; bf[2 * p + 1][1] = r3;
            }
#pragma unroll
            for (int mi = 0; mi < 2; mi++)
#pragma unroll
                for (int ni = 0; ni < 8; ni++)
                    MMA_BF16(acc[mi][ni], a[mi][0], a[mi][1], a[mi][2], a[mi][3],
                             bf[ni][0], bf[ni][1]);
        }
        __syncthreads();
    }

    int r  = lane >> 2;
    int q2 = (lane & 3) * 2;
#pragma unroll
    for (int mi = 0; mi < 2; mi++) {
        int row0 = bm * 128 + warpm * 32 + mi * 16 + r;
#pragma unroll
        for (int ni = 0; ni < 8; ni++) {
            int col = warpn * 64 + ni * 8 + q2;
            float b0 = bias[col], b1 = bias[col + 1];
            size_t o0 = (size_t)row0 * N + col, o1 = (size_t)(row0 + 8) * N + col;
            out[o0]     += acc[mi][ni][0] + b0;
            out[o0 + 1] += acc[mi][ni][1] + b1;
            out[o1]     += acc[mi][ni][2] + b0;
            out[o1 + 1] += acc[mi][ni][3] + b1;
        }
    }
}

// ---------------- launch ----------------
extern "C" void kernel_launch(void* const* d_in, const int* in_sizes, int n_in,
                              void* d_out, int out_size)
{
    (void)in_sizes; (void)n_in; (void)out_size;
    const float* x    = (const float*)d_in[0];
    const float* x1   = (const float*)d_in[1];
    const float* n1g  = (const float*)d_in[3];
    const float* n1b  = (const float*)d_in[4];
    const float* qw   = (const float*)d_in[5];
    const float* qb   = (const float*)d_in[6];
    const float* kvw  = (const float*)d_in[7];
    const float* kvb  = (const float*)d_in[8];
    const float* rpb  = (const float*)d_in[9];
    const float* pw   = (const float*)d_in[10];
    const float* pb   = (const float*)d_in[11];
    const float* n2g  = (const float*)d_in[12];
    const float* n2b  = (const float*)d_in[13];
    const float* f1w  = (const float*)d_in[14];
    const float* f1b  = (const float*)d_in[15];
    const float* f2w  = (const float*)d_in[16];
    const float* f2b  = (const float*)d_in[17];
    float* out = (float*)d_out;

    bf16 *xw, *x1w, *q, *kv, *ao, *h;
    bf16 *qwb, *kvwb, *pwb, *f1wb, *f2wb;
    cudaGetSymbolAddress((void**)&xw,  g_xw);
    cudaGetSymbolAddress((void**)&x1w, g_x1w);
    cudaGetSymbolAddress((void**)&q,   g_q);
    cudaGetSymbolAddress((void**)&kv,  g_kv);
    cudaGetSymbolAddress((void**)&ao,  g_ao);
    cudaGetSymbolAddress((void**)&h,   g_h);
    cudaGetSymbolAddress((void**)&qwb,  g_qwb);
    cudaGetSymbolAddress((void**)&kvwb, g_kvwb);
    cudaGetSymbolAddress((void**)&pwb,  g_pwb);
    cudaGetSymbolAddress((void**)&f1wb, g_f1wb);
    cudaGetSymbolAddress((void**)&f2wb, g_f2wb);

    cudaFuncSetAttribute(gemm192_kernel<0, false>, cudaFuncAttributeMaxDynamicSharedMemorySize, GSM_BYTES);
    cudaFuncSetAttribute(gemm192_kernel<2, false>, cudaFuncAttributeMaxDynamicSharedMemorySize, GSM_BYTES);
    cudaFuncSetAttribute(gemm192_kernel<1, true>,  cudaFuncAttributeMaxDynamicSharedMemorySize, GSM_BYTES);

    cvt_all_kernel<<<(W5 + 255) / 256, 256>>>(qw, kvw, pw, f1w, f2w);
    ln1_gather_kernel<<<MTOK / 8, 256>>>(x, x1, n1g, n1b);
    gemm192_kernel<0, false><<<MTOK / 128, 384, GSM_BYTES>>>(xw,  kvwb, kvb, kv, nullptr, nullptr, nullptr, 384);
    gemm192_kernel<0, false><<<MTOK / 128, 384, GSM_BYTES>>>(x1w, qwb,  qb,  q,  nullptr, nullptr, nullptr, 192);
    attn_kernel<<<BW * HEADS, 128>>>(rpb);
    gemm192_kernel<2, false><<<MTOK / 128, 384, GSM_BYTES>>>(ao, pwb, pb, out, x, nullptr, nullptr, 192);
    gemm192_kernel<1, true><<<MTOK / 128, 384, GSM_BYTES>>>(out, f1wb, f1b, h, nullptr, n2g, n2b, 768);
    gemm_fc2_kernel<<<MTOK / 128, 384>>>(h, f2wb, f2b, out, MTOK, Cc, HID);
}